// round 13
// baseline (speedup 1.0000x reference)
#include <cuda_runtime.h>
#include <cuda_bf16.h>
#include <cuda_fp16.h>
#include <cstdint>
#include <cmath>

// ---------------- problem constants ----------------
#define Bv     64
#define Cv     3
#define IMGv   224
#define Pv     16
#define Sv     8
#define Gv     14
#define NPv    196
#define Nv     197
#define DIMv   384
#define DEPTHv 12
#define Hv     12
#define DHv    32
#define INNERv 384
#define MLPv   1536
#define NCLSv  1000
#define PDv    1792
#define TOK    (Bv*Nv)      // 12608
#define MP     (Bv*NPv)     // 12544
#define EPSv   1e-5f

#define K2_DIM (2*DIMv)     // 768
#define K2_MLP (2*MLPv)     // 3072
#define K2_PD  (2*PDv)      // 3584

// ---------------- scratch (device globals; no allocation allowed) ----------------
__device__ float g_mean [Bv * IMGv * IMGv];
__device__ float g_x    [TOK * DIMv];
__device__ float g_qkv  [TOK * 3 * INNERv];

__device__ __half a2_patch[(size_t)MP  * K2_PD];
__device__ __half a2_h    [(size_t)TOK * K2_DIM];
__device__ __half a2_o    [(size_t)TOK * K2_DIM];
__device__ __half a2_ff   [(size_t)TOK * K2_MLP];
__device__ __half a2_cls  [Bv * K2_DIM];

__device__ __half w2_patch[(size_t)DIMv  * K2_PD];
__device__ __half w2_qkv  [(size_t)DEPTHv * 3*INNERv * K2_DIM];
__device__ __half w2_out  [(size_t)DEPTHv * DIMv     * K2_DIM];
__device__ __half w2_ff1  [(size_t)DEPTHv * MLPv     * K2_DIM];
__device__ __half w2_ff2  [(size_t)DEPTHv * DIMv     * K2_MLP];
__device__ __half w2_head [(size_t)NCLSv * K2_DIM];

// ---------------- small helpers ----------------
__device__ __forceinline__ float gelu_exact(float x) {
    return 0.5f * x * (1.0f + erff(x * 0.70710678118654752440f));
}
__device__ __forceinline__ void split2h(float v, __half& hi, __half& lo) {
    hi = __float2half(v);
    lo = __float2half(v - __half2float(hi));
}
__device__ __forceinline__ uint32_t smem_u32(const void* p) {
    uint32_t a;
    asm("{ .reg .u64 t; cvta.to.shared.u64 t, %1; cvt.u32.u64 %0, t; }" : "=r"(a) : "l"(p));
    return a;
}
__device__ __forceinline__ void cp16(uint32_t dst, const void* src, uint32_t srcsize) {
    asm volatile("cp.async.cg.shared.global [%0], [%1], 16, %2;"
                 :: "r"(dst), "l"(src), "r"(srcsize) : "memory");
}
#define CP_COMMIT() asm volatile("cp.async.commit_group;" ::: "memory")
#define CP_WAIT1()  asm volatile("cp.async.wait_group 1;" ::: "memory")

__device__ __forceinline__ void ldsm4(uint32_t* r, uint32_t addr) {
    asm volatile("ldmatrix.sync.aligned.m8n8.x4.shared.b16 {%0,%1,%2,%3}, [%4];"
                 : "=r"(r[0]), "=r"(r[1]), "=r"(r[2]), "=r"(r[3]) : "r"(addr));
}
__device__ __forceinline__ void mma16816(float* c, const uint32_t* a,
                                         uint32_t b0, uint32_t b1) {
    asm volatile(
        "mma.sync.aligned.m16n8k16.row.col.f32.f16.f16.f32 "
        "{%0,%1,%2,%3}, {%4,%5,%6,%7}, {%8,%9}, {%0,%1,%2,%3};"
        : "+f"(c[0]), "+f"(c[1]), "+f"(c[2]), "+f"(c[3])
        : "r"(a[0]), "r"(a[1]), "r"(a[2]), "r"(a[3]), "r"(b0), "r"(b1));
}

// ---------------- preprocessing kernels ----------------
__global__ void mean_kernel(const float* __restrict__ img) {
    int idx = blockIdx.x * blockDim.x + threadIdx.x;
    if (idx >= Bv * IMGv * IMGv) return;
    int b = idx / (IMGv * IMGv);
    int yx = idx % (IMGv * IMGv);
    const float* p = img + (size_t)b * Cv * IMGv * IMGv + yx;
    g_mean[idx] = (p[0] + p[IMGv * IMGv] + p[2 * IMGv * IMGv]) * (1.0f / 3.0f);
}

__global__ void patch_build_kernel(const float* __restrict__ img) {
    int idx = blockIdx.x * blockDim.x + threadIdx.x;
    if (idx >= MP * PDv) return;
    int pd = idx % PDv;
    int n  = (idx / PDv) % NPv;
    int b  = idx / (PDv * NPv);
    int c  = pd % 7;
    int pp = pd / 7;
    int px = pp % Pv, py = pp / Pv;
    int gy = n / Gv, gx = n % Gv;
    int y = gy * Pv + py, x = gx * Pv + px;
    float v;
    if (c < 3) {
        v = img[(((size_t)b * Cv + c) * IMGv + y) * IMGv + x];
    } else {
        int yy = y, xx = x;
        if      (c == 3) xx = x - Sv;
        else if (c == 4) xx = x + Sv;
        else if (c == 5) yy = y - Sv;
        else             yy = y + Sv;
        v = (xx < 0 || xx >= IMGv || yy < 0 || yy >= IMGv)
                ? 0.0f : g_mean[((size_t)b * IMGv + yy) * IMGv + xx];
    }
    __half hi, lo; split2h(v, hi, lo);
    size_t row = (size_t)(b * NPv + n) * K2_PD;
    a2_patch[row + pd]       = hi;
    a2_patch[row + PDv + pd] = lo;
}

__global__ void cls_init_kernel(const float* __restrict__ cls_tok,
                                const float* __restrict__ pos) {
    int d = threadIdx.x;
    int b = blockIdx.x;
    g_x[(size_t)b * Nv * DIMv + d] = cls_tok[d] + pos[d];
}

// weight convert: src [L][Nr,K] fp32 -> dst [L][Nr,2K] fp16  ([hi|hi])
__global__ void convw_kernel(const float* __restrict__ src, __half* __restrict__ dst,
                             int Nr, int K) {
    int idx = blockIdx.x * 256 + threadIdx.x;
    if (idx >= Nr * K) return;
    src += (size_t)blockIdx.y * Nr * K;
    dst += (size_t)blockIdx.y * Nr * 2 * K;
    int n = idx / K, k = idx % K;
    __half hi = __float2half(src[idx]);
    size_t r = (size_t)n * 2 * K;
    dst[r + k]     = hi;
    dst[r + K + k] = hi;
}

// ---------------- layernorm -> split-fp16 activation ([hi|lo]) ----------------
__global__ void __launch_bounds__(128)
ln_split_kernel(const float* __restrict__ x, const float* __restrict__ g,
                const float* __restrict__ bta, __half* __restrict__ out,
                long in_stride)
{
    long r = blockIdx.x;
    const float* xr = x + r * in_stride;
    int t = threadIdx.x;
    float v0 = xr[t], v1 = xr[t + 128], v2 = xr[t + 256];
    float s1 = v0 + v1 + v2;
    float s2 = v0 * v0 + v1 * v1 + v2 * v2;
    #pragma unroll
    for (int o = 16; o; o >>= 1) {
        s1 += __shfl_xor_sync(0xFFFFFFFFu, s1, o);
        s2 += __shfl_xor_sync(0xFFFFFFFFu, s2, o);
    }
    __shared__ float sh[8];
    int w = t >> 5;
    if ((t & 31) == 0) { sh[w] = s1; sh[4 + w] = s2; }
    __syncthreads();
    s1 = sh[0] + sh[1] + sh[2] + sh[3];
    s2 = sh[4] + sh[5] + sh[6] + sh[7];
    float mu  = s1 * (1.0f / DIMv);
    float var = s2 * (1.0f / DIMv) - mu * mu;
    float rs  = rsqrtf(var + EPSv);
    __half* orow = out + r * (long)K2_DIM;
    #pragma unroll
    for (int q = 0; q < 3; q++) {
        int c = t + q * 128;
        float vv = (q == 0 ? v0 : (q == 1 ? v1 : v2));
        float y = (vv - mu) * rs * g[c] + bta[c];
        __half hi, lo; split2h(y, hi, lo);
        orow[c]        = hi;
        orow[DIMv + c] = lo;
    }
}

// ---------------- attention v3: float4 smem, no online max, SEL diag mask ----------------
__global__ void __launch_bounds__(224)
attn3(const float* __restrict__ scale)
{
    __shared__ float4 Ks[Nv][8];
    __shared__ float4 Vs[Nv][8];
    int h = blockIdx.x % Hv;
    int b = blockIdx.x / Hv;
    const float* base = g_qkv + (size_t)b * Nv * (3 * INNERv) + h * DHv;

    for (int idx = threadIdx.x; idx < Nv * 8; idx += 224) {
        int r = idx >> 3;
        int c = idx & 7;
        const float* row = base + (size_t)r * (3 * INNERv);
        Ks[r][c] = *(const float4*)(row + INNERv + c * 4);
        Vs[r][c] = *(const float4*)(row + 2 * INNERv + c * 4);
    }
    __syncthreads();

    int i = threadIdx.x;
    if (i >= Nv) return;
    float sc = scale[h];
    const float* qrow = base + (size_t)i * (3 * INNERv);
    float4 q[8];
    #pragma unroll
    for (int c = 0; c < 8; c++) {
        float4 v = *(const float4*)(qrow + c * 4);
        q[c] = make_float4(v.x * sc, v.y * sc, v.z * sc, v.w * sc);
    }

    float s = 0.0f;
    float4 acc[8];
    #pragma unroll
    for (int c = 0; c < 8; c++) acc[c] = make_float4(0.f, 0.f, 0.f, 0.f);

    #pragma unroll 2
    for (int j = 0; j < Nv; j++) {
        float d0 = 0.f, d1 = 0.f, d2 = 0.f, d3 = 0.f;
        #pragma unroll
        for (int c = 0; c < 8; c++) {
            float4 k = Ks[j][c];
            d0 = fmaf(q[c].x, k.x, d0);
            d1 = fmaf(q[c].y, k.y, d1);
            d2 = fmaf(q[c].z, k.z, d2);
            d3 = fmaf(q[c].w, k.w, d3);
        }
        float d = (d0 + d1) + (d2 + d3);
        float p = (j == i) ? 0.0f : __expf(d);
        s += p;
        #pragma unroll
        for (int c = 0; c < 8; c++) {
            float4 v = Vs[j][c];
            acc[c].x = fmaf(p, v.x, acc[c].x);
            acc[c].y = fmaf(p, v.y, acc[c].y);
            acc[c].z = fmaf(p, v.z, acc[c].z);
            acc[c].w = fmaf(p, v.w, acc[c].w);
        }
    }

    float inv = 1.0f / s;
    __half* o = a2_o + (size_t)(b * Nv + i) * K2_DIM + h * DHv;
    #pragma unroll
    for (int c = 0; c < 8; c++) {
        float vv[4] = {acc[c].x * inv, acc[c].y * inv, acc[c].z * inv, acc[c].w * inv};
        #pragma unroll
        for (int u = 0; u < 4; u++) {
            __half hi, lo; split2h(vv[u], hi, lo);
            o[c * 4 + u]        = hi;
            o[DIMv + c * 4 + u] = lo;
        }
    }
}

// ---------------- HMMA split-fp16 GEMM: C = A2[M,2K] * W2[N,2K]^T ----------------
// CTA tile 128x128, 8 warps of 64x32, BK=32, 3-stage cp.async ring (wait 1),
// __launch_bounds__(256,3) -> 3 CTAs/SM (regs capped at 85).
#define FLAG_GELU  1
#define FLAG_REMAP 2
#define FLAG_SPLIT 4
#define HSTRIDE 40                       // halves per smem row (80B, conflict-free)
#define HS_B    (128 * HSTRIDE * 2)      // 10240B
#define STAGEB  (2 * 128 * HSTRIDE * 2)  // 20480B
#define NSTAGE  3
#define SMEM_DYN (NSTAGE * STAGEB)       // 61440B

__device__ __forceinline__ void store_pair(
    float v0, float v1, int orow, int gn, int Nn,
    const float* bias, const float* resid, const float* pos,
    float* Cf, __half* Cs, int flags)
{
    if (bias) { v0 += bias[gn]; v1 += bias[gn + 1]; }
    if (flags & FLAG_GELU) { v0 = gelu_exact(v0); v1 = gelu_exact(v1); }
    if (pos) {
        const float* pp = pos + (size_t)(orow % Nv) * Nn + gn;
        v0 += pp[0]; v1 += pp[1];
    }
    if (resid) {
        const float* rr = resid + (size_t)orow * Nn + gn;
        v0 += rr[0]; v1 += rr[1];
    }
    if (flags & FLAG_SPLIT) {
        __half h0, l0, h1, l1;
        split2h(v0, h0, l0); split2h(v1, h1, l1);
        __half* p = Cs + (size_t)orow * 2 * Nn + gn;
        *(__half2*)(p)      = __halves2half2(h0, h1);
        *(__half2*)(p + Nn) = __halves2half2(l0, l1);
    } else {
        *(float2*)(Cf + (size_t)orow * Nn + gn) = make_float2(v0, v1);
    }
}

__global__ void __launch_bounds__(256, 3)
hm_gemm(const __half* __restrict__ A, const __half* __restrict__ W,
        const float* __restrict__ bias, const float* __restrict__ resid,
        const float* __restrict__ pos, float* __restrict__ Cf,
        __half* __restrict__ Cs,
        int M, int Nn, int K2, int flags)
{
    extern __shared__ __align__(16) char sm[];
    uint32_t sbase = smem_u32(sm);
    int tid = threadIdx.x, lane = tid & 31, wid = tid >> 5;
    int m0 = blockIdx.y * 128, n0 = blockIdx.x * 128;
    int wr = wid >> 2, wc = wid & 3;     // warp tile: 64(M) x 32(N)

    float c[4][4][4];
    #pragma unroll
    for (int i = 0; i < 4; i++)
        #pragma unroll
        for (int j = 0; j < 4; j++)
            #pragma unroll
            for (int q = 0; q < 4; q++) c[i][j][q] = 0.0f;

    const int rbase = tid >> 2;          // 0..63
    const int kseg  = (tid & 3) * 8;     // halves

    const int nk = K2 / 32;

    auto load_stage = [&](int slot, int ch) {
        uint32_t sa = sbase + slot * STAGEB;
        int kk = ch * 32;
        #pragma unroll
        for (int i = 0; i < 2; i++) {
            int r = rbase + i * 64;
            uint32_t dst = sa + (uint32_t)(r * HSTRIDE + kseg) * 2;
            const void* src = A + (size_t)(m0 + r) * K2 + kk + kseg;
            cp16(dst, src, (m0 + r < M) ? 16u : 0u);
        }
        #pragma unroll
        for (int i = 0; i < 2; i++) {
            int r = rbase + i * 64;
            uint32_t dst = sa + HS_B + (uint32_t)(r * HSTRIDE + kseg) * 2;
            const void* src = W + (size_t)(n0 + r) * K2 + kk + kseg;
            cp16(dst, src, (n0 + r < Nn) ? 16u : 0u);
        }
        CP_COMMIT();
    };

    // prologue: 2 stages in flight
    load_stage(0, 0);
    load_stage(1, 1);

    int slot = 0;
    for (int ch = 0; ch < nk; ch++) {
        CP_WAIT1();
        __syncthreads();
        if (ch + 2 < nk) {
            int ns = slot + 2; if (ns >= NSTAGE) ns -= NSTAGE;
            load_stage(ns, ch + 2);
        } else {
            CP_COMMIT();
        }

        uint32_t sa = sbase + slot * STAGEB;
        #pragma unroll
        for (int ko = 0; ko < 2; ko++) {
            int col = ko * 16 + ((lane >> 4) << 3);
            uint32_t a[4][4];
            #pragma unroll
            for (int mf = 0; mf < 4; mf++) {
                int row = wr * 64 + mf * 16 + (lane & 15);
                ldsm4(a[mf], sa + (uint32_t)(row * HSTRIDE + col) * 2);
            }
            uint32_t b[2][4];
            #pragma unroll
            for (int p = 0; p < 2; p++) {
                int row = wc * 32 + p * 16 + (lane & 15);
                ldsm4(b[p], sa + HS_B + (uint32_t)(row * HSTRIDE + col) * 2);
            }
            #pragma unroll
            for (int mf = 0; mf < 4; mf++)
                #pragma unroll
                for (int nf = 0; nf < 4; nf++) {
                    int p = nf >> 1, q = nf & 1;
                    mma16816(c[mf][nf], a[mf], b[p][q], b[p][2 + q]);
                }
        }
        if (++slot == NSTAGE) slot = 0;
    }

    // ---- epilogue ----
    #pragma unroll
    for (int mf = 0; mf < 4; mf++) {
        int r0 = m0 + wr * 64 + mf * 16 + (lane >> 2);
        #pragma unroll
        for (int nf = 0; nf < 4; nf++) {
            int gn = n0 + wc * 32 + nf * 8 + (lane & 3) * 2;
            if (gn >= Nn) continue;
            if (r0 < M) {
                int orow = r0;
                if (flags & FLAG_REMAP) { int b = r0 / NPv; orow = r0 + b + 1; }
                store_pair(c[mf][nf][0], c[mf][nf][1], orow, gn, Nn,
                           bias, resid, pos, Cf, Cs, flags);
            }
            int r1 = r0 + 8;
            if (r1 < M) {
                int orow = r1;
                if (flags & FLAG_REMAP) { int b = r1 / NPv; orow = r1 + b + 1; }
                store_pair(c[mf][nf][2], c[mf][nf][3], orow, gn, Nn,
                           bias, resid, pos, Cf, Cs, flags);
            }
        }
    }
}

// ---------------- host side ----------------
static inline void run_hm(const __half* A, const __half* W,
                          const float* bias, const float* resid, const float* pos,
                          float* Cf, __half* Cs,
                          int M, int Nn, int K2, int flags)
{
    dim3 grid((Nn + 127) / 128, (M + 127) / 128);
    hm_gemm<<<grid, 256, SMEM_DYN>>>(A, W, bias, resid, pos, Cf, Cs, M, Nn, K2, flags);
}

extern "C" void kernel_launch(void* const* d_in, const int* in_sizes, int n_in,
                              void* d_out, int out_size)
{
    const float* img     = (const float*)d_in[0];
    const float* patch_w = (const float*)d_in[1];
    const float* patch_b = (const float*)d_in[2];
    const float* pos_emb = (const float*)d_in[3];
    const float* cls_tok = (const float*)d_in[4];
    const float* ln1_g   = (const float*)d_in[5];
    const float* ln1_b   = (const float*)d_in[6];
    const float* qkv_w   = (const float*)d_in[7];
    const float* scale   = (const float*)d_in[8];
    const float* out_w   = (const float*)d_in[9];
    const float* out_b   = (const float*)d_in[10];
    const float* ln2_g   = (const float*)d_in[11];
    const float* ln2_b   = (const float*)d_in[12];
    const float* ff_w1   = (const float*)d_in[13];
    const float* ff_b1   = (const float*)d_in[14];
    const float* ff_w2   = (const float*)d_in[15];
    const float* ff_b2   = (const float*)d_in[16];
    const float* lnf_g   = (const float*)d_in[17];
    const float* lnf_b   = (const float*)d_in[18];
    const float* head_w  = (const float*)d_in[19];
    const float* head_b  = (const float*)d_in[20];

    cudaFuncSetAttribute(hm_gemm, cudaFuncAttributeMaxDynamicSharedMemorySize, SMEM_DYN);

    float *xp, *qkvp;
    __half *a2p, *a2hp, *a2op, *a2fp, *a2cp;
    __half *w2p, *w2q, *w2o, *w2f1, *w2f2, *w2h;
    cudaGetSymbolAddress((void**)&xp,   g_x);
    cudaGetSymbolAddress((void**)&qkvp, g_qkv);
    cudaGetSymbolAddress((void**)&a2p,  a2_patch);
    cudaGetSymbolAddress((void**)&a2hp, a2_h);
    cudaGetSymbolAddress((void**)&a2op, a2_o);
    cudaGetSymbolAddress((void**)&a2fp, a2_ff);
    cudaGetSymbolAddress((void**)&a2cp, a2_cls);
    cudaGetSymbolAddress((void**)&w2p,  w2_patch);
    cudaGetSymbolAddress((void**)&w2q,  w2_qkv);
    cudaGetSymbolAddress((void**)&w2o,  w2_out);
    cudaGetSymbolAddress((void**)&w2f1, w2_ff1);
    cudaGetSymbolAddress((void**)&w2f2, w2_ff2);
    cudaGetSymbolAddress((void**)&w2h,  w2_head);

    {
        int n = Bv * IMGv * IMGv;
        mean_kernel<<<(n + 255) / 256, 256>>>(img);
        int np = MP * PDv;
        patch_build_kernel<<<(np + 255) / 256, 256>>>(img);
        int nw = DIMv * PDv;
        convw_kernel<<<dim3((nw + 255) / 256, 1), 256>>>(patch_w, w2p, DIMv, PDv);
    }
    run_hm(a2p, w2p, patch_b, nullptr, pos_emb, xp, nullptr,
           MP, DIMv, K2_PD, FLAG_REMAP);
    cls_init_kernel<<<Bv, DIMv>>>(cls_tok, pos_emb);

    {
        int n;
        n = 3 * INNERv * DIMv;
        convw_kernel<<<dim3((n + 255) / 256, DEPTHv), 256>>>(qkv_w, w2q, 3 * INNERv, DIMv);
        n = DIMv * INNERv;
        convw_kernel<<<dim3((n + 255) / 256, DEPTHv), 256>>>(out_w, w2o, DIMv, INNERv);
        n = MLPv * DIMv;
        convw_kernel<<<dim3((n + 255) / 256, DEPTHv), 256>>>(ff_w1, w2f1, MLPv, DIMv);
        n = DIMv * MLPv;
        convw_kernel<<<dim3((n + 255) / 256, DEPTHv), 256>>>(ff_w2, w2f2, DIMv, MLPv);
        n = NCLSv * DIMv;
        convw_kernel<<<dim3((n + 255) / 256, 1), 256>>>(head_w, w2h, NCLSv, DIMv);
    }

    for (int L = 0; L < DEPTHv; L++) {
        ln_split_kernel<<<TOK, 128>>>(xp, ln1_g + L * DIMv, ln1_b + L * DIMv, a2hp, DIMv);
        run_hm(a2hp, w2q + (size_t)L * 3 * INNERv * K2_DIM, nullptr, nullptr, nullptr,
               qkvp, nullptr, TOK, 3 * INNERv, K2_DIM, 0);
        attn3<<<Bv * Hv, 224>>>(scale + L * Hv);
        run_hm(a2op, w2o + (size_t)L * DIMv * K2_DIM, out_b + L * DIMv, xp, nullptr,
               xp, nullptr, TOK, DIMv, K2_DIM, 0);
        ln_split_kernel<<<TOK, 128>>>(xp, ln2_g + L * DIMv, ln2_b + L * DIMv, a2hp, DIMv);
        run_hm(a2hp, w2f1 + (size_t)L * MLPv * K2_DIM, ff_b1 + L * MLPv, nullptr, nullptr,
               nullptr, a2fp, TOK, MLPv, K2_DIM, FLAG_GELU | FLAG_SPLIT);
        run_hm(a2fp, w2f2 + (size_t)L * DIMv * K2_MLP, ff_b2 + L * DIMv, xp, nullptr,
               xp, nullptr, TOK, DIMv, K2_MLP, 0);
    }

    // final LN on cls rows (row b = x[b*197*384]) -> split, then head
    ln_split_kernel<<<Bv, 128>>>(xp, lnf_g, lnf_b, a2cp, (long)Nv * DIMv);
    run_hm(a2cp, w2h, head_b, nullptr, nullptr, (float*)d_out, nullptr,
           Bv, NCLSv, K2_DIM, 0);
}

// round 14
// speedup vs baseline: 1.1604x; 1.1604x over previous
#include <cuda_runtime.h>
#include <cuda_bf16.h>
#include <cuda_fp16.h>
#include <cstdint>
#include <cmath>

// ---------------- problem constants ----------------
#define Bv     64
#define Cv     3
#define IMGv   224
#define Pv     16
#define Sv     8
#define Gv     14
#define NPv    196
#define Nv     197
#define DIMv   384
#define DEPTHv 12
#define Hv     12
#define DHv    32
#define INNERv 384
#define MLPv   1536
#define NCLSv  1000
#define PDv    1792
#define TOK    (Bv*Nv)      // 12608
#define MP     (Bv*NPv)     // 12544
#define EPSv   1e-5f

#define K2_DIM (2*DIMv)     // 768
#define K2_MLP (2*MLPv)     // 3072
#define K2_PD  (2*PDv)      // 3584

// ---------------- scratch (device globals; no allocation allowed) ----------------
__device__ float g_mean [Bv * IMGv * IMGv];
__device__ float g_x    [TOK * DIMv];
__device__ float g_qkv  [TOK * 3 * INNERv];

__device__ __half a2_patch[(size_t)MP  * K2_PD];
__device__ __half a2_h    [(size_t)TOK * K2_DIM];
__device__ __half a2_o    [(size_t)TOK * K2_DIM];
__device__ __half a2_ff   [(size_t)TOK * K2_MLP];
__device__ __half a2_cls  [Bv * K2_DIM];

__device__ __half w2_patch[(size_t)DIMv  * K2_PD];
__device__ __half w2_qkv  [(size_t)DEPTHv * 3*INNERv * K2_DIM];
__device__ __half w2_out  [(size_t)DEPTHv * DIMv     * K2_DIM];
__device__ __half w2_ff1  [(size_t)DEPTHv * MLPv     * K2_DIM];
__device__ __half w2_ff2  [(size_t)DEPTHv * DIMv     * K2_MLP];
__device__ __half w2_head [(size_t)NCLSv * K2_DIM];

// ---------------- small helpers ----------------
__device__ __forceinline__ float gelu_exact(float x) {
    return 0.5f * x * (1.0f + erff(x * 0.70710678118654752440f));
}
__device__ __forceinline__ void split2h(float v, __half& hi, __half& lo) {
    hi = __float2half(v);
    lo = __float2half(v - __half2float(hi));
}
__device__ __forceinline__ uint32_t smem_u32(const void* p) {
    uint32_t a;
    asm("{ .reg .u64 t; cvta.to.shared.u64 t, %1; cvt.u32.u64 %0, t; }" : "=r"(a) : "l"(p));
    return a;
}
__device__ __forceinline__ void cp16(uint32_t dst, const void* src, uint32_t srcsize) {
    asm volatile("cp.async.cg.shared.global [%0], [%1], 16, %2;"
                 :: "r"(dst), "l"(src), "r"(srcsize) : "memory");
}
#define CP_COMMIT() asm volatile("cp.async.commit_group;" ::: "memory")
#define CP_WAIT1()  asm volatile("cp.async.wait_group 1;" ::: "memory")

__device__ __forceinline__ void ldsm4(uint32_t* r, uint32_t addr) {
    asm volatile("ldmatrix.sync.aligned.m8n8.x4.shared.b16 {%0,%1,%2,%3}, [%4];"
                 : "=r"(r[0]), "=r"(r[1]), "=r"(r[2]), "=r"(r[3]) : "r"(addr));
}
__device__ __forceinline__ void mma16816(float* c, const uint32_t* a,
                                         uint32_t b0, uint32_t b1) {
    asm volatile(
        "mma.sync.aligned.m16n8k16.row.col.f32.f16.f16.f32 "
        "{%0,%1,%2,%3}, {%4,%5,%6,%7}, {%8,%9}, {%0,%1,%2,%3};"
        : "+f"(c[0]), "+f"(c[1]), "+f"(c[2]), "+f"(c[3])
        : "r"(a[0]), "r"(a[1]), "r"(a[2]), "r"(a[3]), "r"(b0), "r"(b1));
}

// ---------------- preprocessing kernels ----------------
__global__ void mean_kernel(const float* __restrict__ img) {
    int idx = blockIdx.x * blockDim.x + threadIdx.x;
    if (idx >= Bv * IMGv * IMGv) return;
    int b = idx / (IMGv * IMGv);
    int yx = idx % (IMGv * IMGv);
    const float* p = img + (size_t)b * Cv * IMGv * IMGv + yx;
    g_mean[idx] = (p[0] + p[IMGv * IMGv] + p[2 * IMGv * IMGv]) * (1.0f / 3.0f);
}

__global__ void patch_build_kernel(const float* __restrict__ img) {
    int idx = blockIdx.x * blockDim.x + threadIdx.x;
    if (idx >= MP * PDv) return;
    int pd = idx % PDv;
    int n  = (idx / PDv) % NPv;
    int b  = idx / (PDv * NPv);
    int c  = pd % 7;
    int pp = pd / 7;
    int px = pp % Pv, py = pp / Pv;
    int gy = n / Gv, gx = n % Gv;
    int y = gy * Pv + py, x = gx * Pv + px;
    float v;
    if (c < 3) {
        v = img[(((size_t)b * Cv + c) * IMGv + y) * IMGv + x];
    } else {
        int yy = y, xx = x;
        if      (c == 3) xx = x - Sv;
        else if (c == 4) xx = x + Sv;
        else if (c == 5) yy = y - Sv;
        else             yy = y + Sv;
        v = (xx < 0 || xx >= IMGv || yy < 0 || yy >= IMGv)
                ? 0.0f : g_mean[((size_t)b * IMGv + yy) * IMGv + xx];
    }
    __half hi, lo; split2h(v, hi, lo);
    size_t row = (size_t)(b * NPv + n) * K2_PD;
    a2_patch[row + pd]       = hi;
    a2_patch[row + PDv + pd] = lo;
}

__global__ void cls_init_kernel(const float* __restrict__ cls_tok,
                                const float* __restrict__ pos) {
    int d = threadIdx.x;
    int b = blockIdx.x;
    g_x[(size_t)b * Nv * DIMv + d] = cls_tok[d] + pos[d];
}

// weight convert: src [L][Nr,K] fp32 -> dst [L][Nr,2K] fp16  ([hi|hi])
__global__ void convw_kernel(const float* __restrict__ src, __half* __restrict__ dst,
                             int Nr, int K) {
    int idx = blockIdx.x * 256 + threadIdx.x;
    if (idx >= Nr * K) return;
    src += (size_t)blockIdx.y * Nr * K;
    dst += (size_t)blockIdx.y * Nr * 2 * K;
    int n = idx / K, k = idx % K;
    __half hi = __float2half(src[idx]);
    size_t r = (size_t)n * 2 * K;
    dst[r + k]     = hi;
    dst[r + K + k] = hi;
}

// ---------------- layernorm -> split-fp16 activation ([hi|lo]) ----------------
__global__ void __launch_bounds__(128)
ln_split_kernel(const float* __restrict__ x, const float* __restrict__ g,
                const float* __restrict__ bta, __half* __restrict__ out,
                long in_stride)
{
    long r = blockIdx.x;
    const float* xr = x + r * in_stride;
    int t = threadIdx.x;
    float v0 = xr[t], v1 = xr[t + 128], v2 = xr[t + 256];
    float s1 = v0 + v1 + v2;
    float s2 = v0 * v0 + v1 * v1 + v2 * v2;
    #pragma unroll
    for (int o = 16; o; o >>= 1) {
        s1 += __shfl_xor_sync(0xFFFFFFFFu, s1, o);
        s2 += __shfl_xor_sync(0xFFFFFFFFu, s2, o);
    }
    __shared__ float sh[8];
    int w = t >> 5;
    if ((t & 31) == 0) { sh[w] = s1; sh[4 + w] = s2; }
    __syncthreads();
    s1 = sh[0] + sh[1] + sh[2] + sh[3];
    s2 = sh[4] + sh[5] + sh[6] + sh[7];
    float mu  = s1 * (1.0f / DIMv);
    float var = s2 * (1.0f / DIMv) - mu * mu;
    float rs  = rsqrtf(var + EPSv);
    __half* orow = out + r * (long)K2_DIM;
    #pragma unroll
    for (int q = 0; q < 3; q++) {
        int c = t + q * 128;
        float vv = (q == 0 ? v0 : (q == 1 ? v1 : v2));
        float y = (vv - mu) * rs * g[c] + bta[c];
        __half hi, lo; split2h(y, hi, lo);
        orow[c]        = hi;
        orow[DIMv + c] = lo;
    }
}

// ---------------- attention v3: float4 smem, no online max, SEL diag mask ----------------
__global__ void __launch_bounds__(224)
attn3(const float* __restrict__ scale)
{
    __shared__ float4 Ks[Nv][8];
    __shared__ float4 Vs[Nv][8];
    int h = blockIdx.x % Hv;
    int b = blockIdx.x / Hv;
    const float* base = g_qkv + (size_t)b * Nv * (3 * INNERv) + h * DHv;

    for (int idx = threadIdx.x; idx < Nv * 8; idx += 224) {
        int r = idx >> 3;
        int c = idx & 7;
        const float* row = base + (size_t)r * (3 * INNERv);
        Ks[r][c] = *(const float4*)(row + INNERv + c * 4);
        Vs[r][c] = *(const float4*)(row + 2 * INNERv + c * 4);
    }
    __syncthreads();

    int i = threadIdx.x;
    if (i >= Nv) return;
    float sc = scale[h];
    const float* qrow = base + (size_t)i * (3 * INNERv);
    float4 q[8];
    #pragma unroll
    for (int c = 0; c < 8; c++) {
        float4 v = *(const float4*)(qrow + c * 4);
        q[c] = make_float4(v.x * sc, v.y * sc, v.z * sc, v.w * sc);
    }

    float s = 0.0f;
    float4 acc[8];
    #pragma unroll
    for (int c = 0; c < 8; c++) acc[c] = make_float4(0.f, 0.f, 0.f, 0.f);

    #pragma unroll 2
    for (int j = 0; j < Nv; j++) {
        float d0 = 0.f, d1 = 0.f, d2 = 0.f, d3 = 0.f;
        #pragma unroll
        for (int c = 0; c < 8; c++) {
            float4 k = Ks[j][c];
            d0 = fmaf(q[c].x, k.x, d0);
            d1 = fmaf(q[c].y, k.y, d1);
            d2 = fmaf(q[c].z, k.z, d2);
            d3 = fmaf(q[c].w, k.w, d3);
        }
        float d = (d0 + d1) + (d2 + d3);
        float p = (j == i) ? 0.0f : __expf(d);
        s += p;
        #pragma unroll
        for (int c = 0; c < 8; c++) {
            float4 v = Vs[j][c];
            acc[c].x = fmaf(p, v.x, acc[c].x);
            acc[c].y = fmaf(p, v.y, acc[c].y);
            acc[c].z = fmaf(p, v.z, acc[c].z);
            acc[c].w = fmaf(p, v.w, acc[c].w);
        }
    }

    float inv = 1.0f / s;
    __half* o = a2_o + (size_t)(b * Nv + i) * K2_DIM + h * DHv;
    #pragma unroll
    for (int c = 0; c < 8; c++) {
        float vv[4] = {acc[c].x * inv, acc[c].y * inv, acc[c].z * inv, acc[c].w * inv};
        #pragma unroll
        for (int u = 0; u < 4; u++) {
            __half hi, lo; split2h(vv[u], hi, lo);
            o[c * 4 + u]        = hi;
            o[DIMv + c * 4 + u] = lo;
        }
    }
}

// ---------------- HMMA split-fp16 GEMM: C = A2[M,2K] * W2[N,2K]^T ----------------
// CTA tile 64(M)x128(N), 128 threads = 4 warps of 32x64, BK=32,
// 3-stage cp.async ring (wait 1). 4 CTAs/SM (46KB smem, ~110 regs) -> 16 warps/SM,
// wave capacity 592 CTAs: proj/ff2/patch grids = 591 = exactly 1 wave.
#define FLAG_GELU  1
#define FLAG_REMAP 2
#define FLAG_SPLIT 4
#define HSTRIDE 40                       // halves per smem row (80B, conflict-free)
#define HS_A    (64 * HSTRIDE * 2)       // 5120B  (A: 64 rows)
#define STAGEB  (HS_A + 128 * HSTRIDE * 2) // 15360B (B: 128 rows)
#define NSTAGE  3
#define SMEM_DYN (NSTAGE * STAGEB)       // 46080B

__device__ __forceinline__ void store_pair(
    float v0, float v1, int orow, int gn, int Nn,
    const float* bias, const float* resid, const float* pos,
    float* Cf, __half* Cs, int flags)
{
    if (bias) { v0 += bias[gn]; v1 += bias[gn + 1]; }
    if (flags & FLAG_GELU) { v0 = gelu_exact(v0); v1 = gelu_exact(v1); }
    if (pos) {
        const float* pp = pos + (size_t)(orow % Nv) * Nn + gn;
        v0 += pp[0]; v1 += pp[1];
    }
    if (resid) {
        const float* rr = resid + (size_t)orow * Nn + gn;
        v0 += rr[0]; v1 += rr[1];
    }
    if (flags & FLAG_SPLIT) {
        __half h0, l0, h1, l1;
        split2h(v0, h0, l0); split2h(v1, h1, l1);
        __half* p = Cs + (size_t)orow * 2 * Nn + gn;
        *(__half2*)(p)      = __halves2half2(h0, h1);
        *(__half2*)(p + Nn) = __halves2half2(l0, l1);
    } else {
        *(float2*)(Cf + (size_t)orow * Nn + gn) = make_float2(v0, v1);
    }
}

__global__ void __launch_bounds__(128, 4)
hm_gemm(const __half* __restrict__ A, const __half* __restrict__ W,
        const float* __restrict__ bias, const float* __restrict__ resid,
        const float* __restrict__ pos, float* __restrict__ Cf,
        __half* __restrict__ Cs,
        int M, int Nn, int K2, int flags)
{
    extern __shared__ __align__(16) char sm[];
    uint32_t sbase = smem_u32(sm);
    int tid = threadIdx.x, lane = tid & 31, wid = tid >> 5;  // 4 warps
    int m0 = blockIdx.y * 64, n0 = blockIdx.x * 128;
    int wr = wid >> 1, wc = wid & 1;     // warp tile: 32(M) x 64(N)

    float c[2][8][4];
    #pragma unroll
    for (int i = 0; i < 2; i++)
        #pragma unroll
        for (int j = 0; j < 8; j++)
            #pragma unroll
            for (int q = 0; q < 4; q++) c[i][j][q] = 0.0f;

    const int rbase = tid >> 2;          // 0..31
    const int kseg  = (tid & 3) * 8;     // halves

    const int nk = K2 / 32;

    auto load_stage = [&](int slot, int ch) {
        uint32_t sa = sbase + slot * STAGEB;
        int kk = ch * 32;
        #pragma unroll
        for (int i = 0; i < 2; i++) {
            int r = rbase + i * 32;
            uint32_t dst = sa + (uint32_t)(r * HSTRIDE + kseg) * 2;
            const void* src = A + (size_t)(m0 + r) * K2 + kk + kseg;
            cp16(dst, src, (m0 + r < M) ? 16u : 0u);
        }
        #pragma unroll
        for (int i = 0; i < 4; i++) {
            int r = rbase + i * 32;
            uint32_t dst = sa + HS_A + (uint32_t)(r * HSTRIDE + kseg) * 2;
            const void* src = W + (size_t)(n0 + r) * K2 + kk + kseg;
            cp16(dst, src, (n0 + r < Nn) ? 16u : 0u);
        }
        CP_COMMIT();
    };

    // prologue: 2 stages in flight
    load_stage(0, 0);
    load_stage(1, 1);

    int slot = 0;
    for (int ch = 0; ch < nk; ch++) {
        CP_WAIT1();
        __syncthreads();
        if (ch + 2 < nk) {
            int ns = slot + 2; if (ns >= NSTAGE) ns -= NSTAGE;
            load_stage(ns, ch + 2);
        } else {
            CP_COMMIT();
        }

        uint32_t sa = sbase + slot * STAGEB;
        #pragma unroll
        for (int ko = 0; ko < 2; ko++) {
            int col = ko * 16 + ((lane >> 4) << 3);
            uint32_t a[2][4];
            #pragma unroll
            for (int mf = 0; mf < 2; mf++) {
                int row = wr * 32 + mf * 16 + (lane & 15);
                ldsm4(a[mf], sa + (uint32_t)(row * HSTRIDE + col) * 2);
            }
            uint32_t b[4][4];
            #pragma unroll
            for (int p = 0; p < 4; p++) {
                int row = wc * 64 + p * 16 + (lane & 15);
                ldsm4(b[p], sa + HS_A + (uint32_t)(row * HSTRIDE + col) * 2);
            }
            #pragma unroll
            for (int mf = 0; mf < 2; mf++)
                #pragma unroll
                for (int nf = 0; nf < 8; nf++) {
                    int p = nf >> 1, q = nf & 1;
                    mma16816(c[mf][nf], a[mf], b[p][q], b[p][2 + q]);
                }
        }
        if (++slot == NSTAGE) slot = 0;
    }

    // ---- epilogue ----
    #pragma unroll
    for (int mf = 0; mf < 2; mf++) {
        int r0 = m0 + wr * 32 + mf * 16 + (lane >> 2);
        #pragma unroll
        for (int nf = 0; nf < 8; nf++) {
            int gn = n0 + wc * 64 + nf * 8 + (lane & 3) * 2;
            if (gn >= Nn) continue;
            if (r0 < M) {
                int orow = r0;
                if (flags & FLAG_REMAP) { int b = r0 / NPv; orow = r0 + b + 1; }
                store_pair(c[mf][nf][0], c[mf][nf][1], orow, gn, Nn,
                           bias, resid, pos, Cf, Cs, flags);
            }
            int r1 = r0 + 8;
            if (r1 < M) {
                int orow = r1;
                if (flags & FLAG_REMAP) { int b = r1 / NPv; orow = r1 + b + 1; }
                store_pair(c[mf][nf][2], c[mf][nf][3], orow, gn, Nn,
                           bias, resid, pos, Cf, Cs, flags);
            }
        }
    }
}

// ---------------- host side ----------------
static inline void run_hm(const __half* A, const __half* W,
                          const float* bias, const float* resid, const float* pos,
                          float* Cf, __half* Cs,
                          int M, int Nn, int K2, int flags)
{
    dim3 grid((Nn + 127) / 128, (M + 63) / 64);
    hm_gemm<<<grid, 128, SMEM_DYN>>>(A, W, bias, resid, pos, Cf, Cs, M, Nn, K2, flags);
}

extern "C" void kernel_launch(void* const* d_in, const int* in_sizes, int n_in,
                              void* d_out, int out_size)
{
    const float* img     = (const float*)d_in[0];
    const float* patch_w = (const float*)d_in[1];
    const float* patch_b = (const float*)d_in[2];
    const float* pos_emb = (const float*)d_in[3];
    const float* cls_tok = (const float*)d_in[4];
    const float* ln1_g   = (const float*)d_in[5];
    const float* ln1_b   = (const float*)d_in[6];
    const float* qkv_w   = (const float*)d_in[7];
    const float* scale   = (const float*)d_in[8];
    const float* out_w   = (const float*)d_in[9];
    const float* out_b   = (const float*)d_in[10];
    const float* ln2_g   = (const float*)d_in[11];
    const float* ln2_b   = (const float*)d_in[12];
    const float* ff_w1   = (const float*)d_in[13];
    const float* ff_b1   = (const float*)d_in[14];
    const float* ff_w2   = (const float*)d_in[15];
    const float* ff_b2   = (const float*)d_in[16];
    const float* lnf_g   = (const float*)d_in[17];
    const float* lnf_b   = (const float*)d_in[18];
    const float* head_w  = (const float*)d_in[19];
    const float* head_b  = (const float*)d_in[20];

    cudaFuncSetAttribute(hm_gemm, cudaFuncAttributeMaxDynamicSharedMemorySize, SMEM_DYN);

    float *xp, *qkvp;
    __half *a2p, *a2hp, *a2op, *a2fp, *a2cp;
    __half *w2p, *w2q, *w2o, *w2f1, *w2f2, *w2h;
    cudaGetSymbolAddress((void**)&xp,   g_x);
    cudaGetSymbolAddress((void**)&qkvp, g_qkv);
    cudaGetSymbolAddress((void**)&a2p,  a2_patch);
    cudaGetSymbolAddress((void**)&a2hp, a2_h);
    cudaGetSymbolAddress((void**)&a2op, a2_o);
    cudaGetSymbolAddress((void**)&a2fp, a2_ff);
    cudaGetSymbolAddress((void**)&a2cp, a2_cls);
    cudaGetSymbolAddress((void**)&w2p,  w2_patch);
    cudaGetSymbolAddress((void**)&w2q,  w2_qkv);
    cudaGetSymbolAddress((void**)&w2o,  w2_out);
    cudaGetSymbolAddress((void**)&w2f1, w2_ff1);
    cudaGetSymbolAddress((void**)&w2f2, w2_ff2);
    cudaGetSymbolAddress((void**)&w2h,  w2_head);

    {
        int n = Bv * IMGv * IMGv;
        mean_kernel<<<(n + 255) / 256, 256>>>(img);
        int np = MP * PDv;
        patch_build_kernel<<<(np + 255) / 256, 256>>>(img);
        int nw = DIMv * PDv;
        convw_kernel<<<dim3((nw + 255) / 256, 1), 256>>>(patch_w, w2p, DIMv, PDv);
    }
    run_hm(a2p, w2p, patch_b, nullptr, pos_emb, xp, nullptr,
           MP, DIMv, K2_PD, FLAG_REMAP);
    cls_init_kernel<<<Bv, DIMv>>>(cls_tok, pos_emb);

    {
        int n;
        n = 3 * INNERv * DIMv;
        convw_kernel<<<dim3((n + 255) / 256, DEPTHv), 256>>>(qkv_w, w2q, 3 * INNERv, DIMv);
        n = DIMv * INNERv;
        convw_kernel<<<dim3((n + 255) / 256, DEPTHv), 256>>>(out_w, w2o, DIMv, INNERv);
        n = MLPv * DIMv;
        convw_kernel<<<dim3((n + 255) / 256, DEPTHv), 256>>>(ff_w1, w2f1, MLPv, DIMv);
        n = DIMv * MLPv;
        convw_kernel<<<dim3((n + 255) / 256, DEPTHv), 256>>>(ff_w2, w2f2, DIMv, MLPv);
        n = NCLSv * DIMv;
        convw_kernel<<<dim3((n + 255) / 256, 1), 256>>>(head_w, w2h, NCLSv, DIMv);
    }

    for (int L = 0; L < DEPTHv; L++) {
        ln_split_kernel<<<TOK, 128>>>(xp, ln1_g + L * DIMv, ln1_b + L * DIMv, a2hp, DIMv);
        run_hm(a2hp, w2q + (size_t)L * 3 * INNERv * K2_DIM, nullptr, nullptr, nullptr,
               qkvp, nullptr, TOK, 3 * INNERv, K2_DIM, 0);
        attn3<<<Bv * Hv, 224>>>(scale + L * Hv);
        run_hm(a2op, w2o + (size_t)L * DIMv * K2_DIM, out_b + L * DIMv, xp, nullptr,
               xp, nullptr, TOK, DIMv, K2_DIM, 0);
        ln_split_kernel<<<TOK, 128>>>(xp, ln2_g + L * DIMv, ln2_b + L * DIMv, a2hp, DIMv);
        run_hm(a2hp, w2f1 + (size_t)L * MLPv * K2_DIM, ff_b1 + L * MLPv, nullptr, nullptr,
               nullptr, a2fp, TOK, MLPv, K2_DIM, FLAG_GELU | FLAG_SPLIT);
        run_hm(a2fp, w2f2 + (size_t)L * DIMv * K2_MLP, ff_b2 + L * DIMv, xp, nullptr,
               xp, nullptr, TOK, DIMv, K2_MLP, 0);
    }

    // final LN on cls rows (row b = x[b*197*384]) -> split, then head
    ln_split_kernel<<<Bv, 128>>>(xp, lnf_g, lnf_b, a2cp, (long)Nv * DIMv);
    run_hm(a2cp, w2h, head_b, nullptr, nullptr, (float*)d_out, nullptr,
           Bv, NCLSv, K2_DIM, 0);
}

// round 15
// speedup vs baseline: 1.1721x; 1.0100x over previous
#include <cuda_runtime.h>
#include <cuda_bf16.h>
#include <cuda_fp16.h>
#include <cstdint>
#include <cmath>

// ---------------- problem constants ----------------
#define Bv     64
#define Cv     3
#define IMGv   224
#define Pv     16
#define Sv     8
#define Gv     14
#define NPv    196
#define Nv     197
#define DIMv   384
#define DEPTHv 12
#define Hv     12
#define DHv    32
#define INNERv 384
#define MLPv   1536
#define NCLSv  1000
#define PDv    1792
#define TOK    (Bv*Nv)      // 12608
#define MP     (Bv*NPv)     // 12544
#define EPSv   1e-5f

#define K2_DIM (2*DIMv)     // 768
#define K2_MLP (2*MLPv)     // 3072
#define K2_PD  (2*PDv)      // 3584

// ---------------- scratch (device globals; no allocation allowed) ----------------
__device__ float g_mean [Bv * IMGv * IMGv];
__device__ float g_x    [TOK * DIMv];
__device__ __half g_qkvh[TOK * 3 * INNERv];   // fp16 qkv

__device__ __half a2_patch[(size_t)MP  * K2_PD];
__device__ __half a2_h    [(size_t)TOK * K2_DIM];
__device__ __half a2_o    [(size_t)TOK * K2_DIM];
__device__ __half a2_ff   [(size_t)TOK * K2_MLP];
__device__ __half a2_cls  [Bv * K2_DIM];

__device__ __half w2_patch[(size_t)DIMv  * K2_PD];
__device__ __half w2_qkv  [(size_t)DEPTHv * 3*INNERv * K2_DIM];
__device__ __half w2_out  [(size_t)DEPTHv * DIMv     * K2_DIM];
__device__ __half w2_ff1  [(size_t)DEPTHv * MLPv     * K2_DIM];
__device__ __half w2_ff2  [(size_t)DEPTHv * DIMv     * K2_MLP];
__device__ __half w2_head [(size_t)NCLSv * K2_DIM];

// ---------------- small helpers ----------------
__device__ __forceinline__ float gelu_exact(float x) {
    return 0.5f * x * (1.0f + erff(x * 0.70710678118654752440f));
}
__device__ __forceinline__ void split2h(float v, __half& hi, __half& lo) {
    hi = __float2half(v);
    lo = __float2half(v - __half2float(hi));
}
__device__ __forceinline__ uint32_t smem_u32(const void* p) {
    uint32_t a;
    asm("{ .reg .u64 t; cvta.to.shared.u64 t, %1; cvt.u32.u64 %0, t; }" : "=r"(a) : "l"(p));
    return a;
}
__device__ __forceinline__ void cp16(uint32_t dst, const void* src, uint32_t srcsize) {
    asm volatile("cp.async.cg.shared.global [%0], [%1], 16, %2;"
                 :: "r"(dst), "l"(src), "r"(srcsize) : "memory");
}
#define CP_COMMIT() asm volatile("cp.async.commit_group;" ::: "memory")
#define CP_WAIT2()  asm volatile("cp.async.wait_group 2;" ::: "memory")

__device__ __forceinline__ void ldsm4(uint32_t* r, uint32_t addr) {
    asm volatile("ldmatrix.sync.aligned.m8n8.x4.shared.b16 {%0,%1,%2,%3}, [%4];"
                 : "=r"(r[0]), "=r"(r[1]), "=r"(r[2]), "=r"(r[3]) : "r"(addr));
}
__device__ __forceinline__ void mma16816(float* c, const uint32_t* a,
                                         uint32_t b0, uint32_t b1) {
    asm volatile(
        "mma.sync.aligned.m16n8k16.row.col.f32.f16.f16.f32 "
        "{%0,%1,%2,%3}, {%4,%5,%6,%7}, {%8,%9}, {%0,%1,%2,%3};"
        : "+f"(c[0]), "+f"(c[1]), "+f"(c[2]), "+f"(c[3])
        : "r"(a[0]), "r"(a[1]), "r"(a[2]), "r"(a[3]), "r"(b0), "r"(b1));
}

// ---------------- preprocessing kernels ----------------
__global__ void mean_kernel(const float* __restrict__ img) {
    int idx = blockIdx.x * blockDim.x + threadIdx.x;
    if (idx >= Bv * IMGv * IMGv) return;
    int b = idx / (IMGv * IMGv);
    int yx = idx % (IMGv * IMGv);
    const float* p = img + (size_t)b * Cv * IMGv * IMGv + yx;
    g_mean[idx] = (p[0] + p[IMGv * IMGv] + p[2 * IMGv * IMGv]) * (1.0f / 3.0f);
}

__global__ void patch_build_kernel(const float* __restrict__ img) {
    int idx = blockIdx.x * blockDim.x + threadIdx.x;
    if (idx >= MP * PDv) return;
    int pd = idx % PDv;
    int n  = (idx / PDv) % NPv;
    int b  = idx / (PDv * NPv);
    int c  = pd % 7;
    int pp = pd / 7;
    int px = pp % Pv, py = pp / Pv;
    int gy = n / Gv, gx = n % Gv;
    int y = gy * Pv + py, x = gx * Pv + px;
    float v;
    if (c < 3) {
        v = img[(((size_t)b * Cv + c) * IMGv + y) * IMGv + x];
    } else {
        int yy = y, xx = x;
        if      (c == 3) xx = x - Sv;
        else if (c == 4) xx = x + Sv;
        else if (c == 5) yy = y - Sv;
        else             yy = y + Sv;
        v = (xx < 0 || xx >= IMGv || yy < 0 || yy >= IMGv)
                ? 0.0f : g_mean[((size_t)b * IMGv + yy) * IMGv + xx];
    }
    __half hi, lo; split2h(v, hi, lo);
    size_t row = (size_t)(b * NPv + n) * K2_PD;
    a2_patch[row + pd]       = hi;
    a2_patch[row + PDv + pd] = lo;
}

__global__ void cls_init_kernel(const float* __restrict__ cls_tok,
                                const float* __restrict__ pos) {
    int d = threadIdx.x;
    int b = blockIdx.x;
    g_x[(size_t)b * Nv * DIMv + d] = cls_tok[d] + pos[d];
}

// weight convert: src [L][Nr,K] fp32 -> dst [L][Nr,2K] fp16  ([hi|hi])
__global__ void convw_kernel(const float* __restrict__ src, __half* __restrict__ dst,
                             int Nr, int K) {
    int idx = blockIdx.x * 256 + threadIdx.x;
    if (idx >= Nr * K) return;
    src += (size_t)blockIdx.y * Nr * K;
    dst += (size_t)blockIdx.y * Nr * 2 * K;
    int n = idx / K, k = idx % K;
    __half hi = __float2half(src[idx]);
    size_t r = (size_t)n * 2 * K;
    dst[r + k]     = hi;
    dst[r + K + k] = hi;
}

// ---------------- layernorm -> split-fp16 activation ([hi|lo]) ----------------
__global__ void __launch_bounds__(128)
ln_split_kernel(const float* __restrict__ x, const float* __restrict__ g,
                const float* __restrict__ bta, __half* __restrict__ out,
                long in_stride)
{
    long r = blockIdx.x;
    const float* xr = x + r * in_stride;
    int t = threadIdx.x;
    float v0 = xr[t], v1 = xr[t + 128], v2 = xr[t + 256];
    float s1 = v0 + v1 + v2;
    float s2 = v0 * v0 + v1 * v1 + v2 * v2;
    #pragma unroll
    for (int o = 16; o; o >>= 1) {
        s1 += __shfl_xor_sync(0xFFFFFFFFu, s1, o);
        s2 += __shfl_xor_sync(0xFFFFFFFFu, s2, o);
    }
    __shared__ float sh[8];
    int w = t >> 5;
    if ((t & 31) == 0) { sh[w] = s1; sh[4 + w] = s2; }
    __syncthreads();
    s1 = sh[0] + sh[1] + sh[2] + sh[3];
    s2 = sh[4] + sh[5] + sh[6] + sh[7];
    float mu  = s1 * (1.0f / DIMv);
    float var = s2 * (1.0f / DIMv) - mu * mu;
    float rs  = rsqrtf(var + EPSv);
    __half* orow = out + r * (long)K2_DIM;
    #pragma unroll
    for (int q = 0; q < 3; q++) {
        int c = t + q * 128;
        float vv = (q == 0 ? v0 : (q == 1 ? v1 : v2));
        float y = (vv - mu) * rs * g[c] + bta[c];
        __half hi, lo; split2h(y, hi, lo);
        orow[c]        = hi;
        orow[DIMv + c] = lo;
    }
}

// ---------------- attention v4: fp16 qkv in global; fp32 smem/compute ----------------
__global__ void __launch_bounds__(224)
attn4(const float* __restrict__ scale)
{
    __shared__ float4 Ks[Nv][8];
    __shared__ float4 Vs[Nv][8];
    int h = blockIdx.x % Hv;
    int b = blockIdx.x / Hv;
    const __half* base = g_qkvh + (size_t)b * Nv * (3 * INNERv) + h * DHv;

    // fill smem (convert fp16 -> fp32 once)
    for (int idx = threadIdx.x; idx < Nv * 4; idx += 224) {
        int r = idx >> 2;
        int c = idx & 3;             // 8 halves per chunk
        const __half* row = base + (size_t)r * (3 * INNERv);
        __half2 k0 = *(const __half2*)(row + INNERv + c * 8);
        __half2 k1 = *(const __half2*)(row + INNERv + c * 8 + 2);
        __half2 k2 = *(const __half2*)(row + INNERv + c * 8 + 4);
        __half2 k3 = *(const __half2*)(row + INNERv + c * 8 + 6);
        float2 a0 = __half22float2(k0), a1 = __half22float2(k1);
        float2 a2 = __half22float2(k2), a3 = __half22float2(k3);
        Ks[r][c * 2]     = make_float4(a0.x, a0.y, a1.x, a1.y);
        Ks[r][c * 2 + 1] = make_float4(a2.x, a2.y, a3.x, a3.y);
        __half2 v0 = *(const __half2*)(row + 2 * INNERv + c * 8);
        __half2 v1 = *(const __half2*)(row + 2 * INNERv + c * 8 + 2);
        __half2 v2 = *(const __half2*)(row + 2 * INNERv + c * 8 + 4);
        __half2 v3 = *(const __half2*)(row + 2 * INNERv + c * 8 + 6);
        float2 b0 = __half22float2(v0), b1 = __half22float2(v1);
        float2 b2 = __half22float2(v2), b3 = __half22float2(v3);
        Vs[r][c * 2]     = make_float4(b0.x, b0.y, b1.x, b1.y);
        Vs[r][c * 2 + 1] = make_float4(b2.x, b2.y, b3.x, b3.y);
    }
    __syncthreads();

    int i = threadIdx.x;
    if (i >= Nv) return;
    float sc = scale[h];
    const __half* qrow = base + (size_t)i * (3 * INNERv);
    float4 q[8];
    #pragma unroll
    for (int c = 0; c < 8; c++) {
        __half2 h0 = *(const __half2*)(qrow + c * 4);
        __half2 h1 = *(const __half2*)(qrow + c * 4 + 2);
        float2 f0 = __half22float2(h0), f1 = __half22float2(h1);
        q[c] = make_float4(f0.x * sc, f0.y * sc, f1.x * sc, f1.y * sc);
    }

    float s = 0.0f;
    float4 acc[8];
    #pragma unroll
    for (int c = 0; c < 8; c++) acc[c] = make_float4(0.f, 0.f, 0.f, 0.f);

    #pragma unroll 2
    for (int j = 0; j < Nv; j++) {
        float d0 = 0.f, d1 = 0.f, d2 = 0.f, d3 = 0.f;
        #pragma unroll
        for (int c = 0; c < 8; c++) {
            float4 k = Ks[j][c];
            d0 = fmaf(q[c].x, k.x, d0);
            d1 = fmaf(q[c].y, k.y, d1);
            d2 = fmaf(q[c].z, k.z, d2);
            d3 = fmaf(q[c].w, k.w, d3);
        }
        float d = (d0 + d1) + (d2 + d3);
        float p = (j == i) ? 0.0f : __expf(d);
        s += p;
        #pragma unroll
        for (int c = 0; c < 8; c++) {
            float4 v = Vs[j][c];
            acc[c].x = fmaf(p, v.x, acc[c].x);
            acc[c].y = fmaf(p, v.y, acc[c].y);
            acc[c].z = fmaf(p, v.z, acc[c].z);
            acc[c].w = fmaf(p, v.w, acc[c].w);
        }
    }

    float inv = 1.0f / s;
    __half* o = a2_o + (size_t)(b * Nv + i) * K2_DIM + h * DHv;
    #pragma unroll
    for (int c = 0; c < 8; c++) {
        float vv[4] = {acc[c].x * inv, acc[c].y * inv, acc[c].z * inv, acc[c].w * inv};
        #pragma unroll
        for (int u = 0; u < 4; u++) {
            __half hi, lo; split2h(vv[u], hi, lo);
            o[c * 4 + u]        = hi;
            o[DIMv + c * 4 + u] = lo;
        }
    }
}

// ---------------- HMMA split-fp16 GEMM: C = A2[M,2K] * W2[N,2K]^T ----------------
// R12 config: CTA 128x128, 8 warps of 64x32, BK=32, 4-stage ring, single sync.
#define FLAG_GELU  1
#define FLAG_REMAP 2
#define FLAG_SPLIT 4
#define FLAG_HALF  8
#define HSTRIDE 40                       // halves per smem row (80B, conflict-free)
#define HS_B    (128 * HSTRIDE * 2)      // 10240B
#define STAGEB  (2 * 128 * HSTRIDE * 2)  // 20480B
#define NSTAGE  4
#define SMEM_DYN (NSTAGE * STAGEB)       // 81920B

__device__ __forceinline__ void store_pair(
    float v0, float v1, int orow, int gn, int Nn,
    const float* bias, const float* resid, const float* pos,
    float* Cf, __half* Cs, int flags)
{
    if (bias) { v0 += bias[gn]; v1 += bias[gn + 1]; }
    if (flags & FLAG_GELU) { v0 = gelu_exact(v0); v1 = gelu_exact(v1); }
    if (pos) {
        const float* pp = pos + (size_t)(orow % Nv) * Nn + gn;
        v0 += pp[0]; v1 += pp[1];
    }
    if (resid) {
        const float* rr = resid + (size_t)orow * Nn + gn;
        v0 += rr[0]; v1 += rr[1];
    }
    if (flags & FLAG_SPLIT) {
        __half h0, l0, h1, l1;
        split2h(v0, h0, l0); split2h(v1, h1, l1);
        __half* p = Cs + (size_t)orow * 2 * Nn + gn;
        *(__half2*)(p)      = __halves2half2(h0, h1);
        *(__half2*)(p + Nn) = __halves2half2(l0, l1);
    } else if (flags & FLAG_HALF) {
        *(__half2*)(Cs + (size_t)orow * Nn + gn) =
            __halves2half2(__float2half(v0), __float2half(v1));
    } else {
        *(float2*)(Cf + (size_t)orow * Nn + gn) = make_float2(v0, v1);
    }
}

__global__ void __launch_bounds__(256, 2)
hm_gemm(const __half* __restrict__ A, const __half* __restrict__ W,
        const float* __restrict__ bias, const float* __restrict__ resid,
        const float* __restrict__ pos, float* __restrict__ Cf,
        __half* __restrict__ Cs,
        int M, int Nn, int K2, int flags)
{
    extern __shared__ __align__(16) char sm[];
    uint32_t sbase = smem_u32(sm);
    int tid = threadIdx.x, lane = tid & 31, wid = tid >> 5;
    int m0 = blockIdx.y * 128, n0 = blockIdx.x * 128;
    int wr = wid >> 2, wc = wid & 3;     // warp tile: 64(M) x 32(N)

    float c[4][4][4];
    #pragma unroll
    for (int i = 0; i < 4; i++)
        #pragma unroll
        for (int j = 0; j < 4; j++)
            #pragma unroll
            for (int q = 0; q < 4; q++) c[i][j][q] = 0.0f;

    const int rbase = tid >> 2;          // 0..63
    const int kseg  = (tid & 3) * 8;     // halves

    const int nk = K2 / 32;

    auto load_stage = [&](int slot, int ch) {
        uint32_t sa = sbase + slot * STAGEB;
        int kk = ch * 32;
        #pragma unroll
        for (int i = 0; i < 2; i++) {
            int r = rbase + i * 64;
            uint32_t dst = sa + (uint32_t)(r * HSTRIDE + kseg) * 2;
            const void* src = A + (size_t)(m0 + r) * K2 + kk + kseg;
            cp16(dst, src, (m0 + r < M) ? 16u : 0u);
        }
        #pragma unroll
        for (int i = 0; i < 2; i++) {
            int r = rbase + i * 64;
            uint32_t dst = sa + HS_B + (uint32_t)(r * HSTRIDE + kseg) * 2;
            const void* src = W + (size_t)(n0 + r) * K2 + kk + kseg;
            cp16(dst, src, (n0 + r < Nn) ? 16u : 0u);
        }
        CP_COMMIT();
    };

    #pragma unroll
    for (int s = 0; s < NSTAGE - 1; s++) load_stage(s, s);   // nk >= 3 always

    for (int ch = 0; ch < nk; ch++) {
        CP_WAIT2();
        __syncthreads();
        if (ch + NSTAGE - 1 < nk) load_stage((ch + NSTAGE - 1) & 3, ch + NSTAGE - 1);
        else CP_COMMIT();

        uint32_t sa = sbase + (ch & 3) * STAGEB;
        #pragma unroll
        for (int ko = 0; ko < 2; ko++) {
            int col = ko * 16 + ((lane >> 4) << 3);
            uint32_t a[4][4];
            #pragma unroll
            for (int mf = 0; mf < 4; mf++) {
                int row = wr * 64 + mf * 16 + (lane & 15);
                ldsm4(a[mf], sa + (uint32_t)(row * HSTRIDE + col) * 2);
            }
            uint32_t b[2][4];
            #pragma unroll
            for (int p = 0; p < 2; p++) {
                int row = wc * 32 + p * 16 + (lane & 15);
                ldsm4(b[p], sa + HS_B + (uint32_t)(row * HSTRIDE + col) * 2);
            }
            #pragma unroll
            for (int mf = 0; mf < 4; mf++)
                #pragma unroll
                for (int nf = 0; nf < 4; nf++) {
                    int p = nf >> 1, q = nf & 1;
                    mma16816(c[mf][nf], a[mf], b[p][q], b[p][2 + q]);
                }
        }
    }

    // ---- epilogue ----
    #pragma unroll
    for (int mf = 0; mf < 4; mf++) {
        int r0 = m0 + wr * 64 + mf * 16 + (lane >> 2);
        #pragma unroll
        for (int nf = 0; nf < 4; nf++) {
            int gn = n0 + wc * 32 + nf * 8 + (lane & 3) * 2;
            if (gn >= Nn) continue;
            if (r0 < M) {
                int orow = r0;
                if (flags & FLAG_REMAP) { int b = r0 / NPv; orow = r0 + b + 1; }
                store_pair(c[mf][nf][0], c[mf][nf][1], orow, gn, Nn,
                           bias, resid, pos, Cf, Cs, flags);
            }
            int r1 = r0 + 8;
            if (r1 < M) {
                int orow = r1;
                if (flags & FLAG_REMAP) { int b = r1 / NPv; orow = r1 + b + 1; }
                store_pair(c[mf][nf][2], c[mf][nf][3], orow, gn, Nn,
                           bias, resid, pos, Cf, Cs, flags);
            }
        }
    }
}

// ---------------- host side ----------------
static inline void run_hm(const __half* A, const __half* W,
                          const float* bias, const float* resid, const float* pos,
                          float* Cf, __half* Cs,
                          int M, int Nn, int K2, int flags)
{
    dim3 grid((Nn + 127) / 128, (M + 127) / 128);
    hm_gemm<<<grid, 256, SMEM_DYN>>>(A, W, bias, resid, pos, Cf, Cs, M, Nn, K2, flags);
}

extern "C" void kernel_launch(void* const* d_in, const int* in_sizes, int n_in,
                              void* d_out, int out_size)
{
    const float* img     = (const float*)d_in[0];
    const float* patch_w = (const float*)d_in[1];
    const float* patch_b = (const float*)d_in[2];
    const float* pos_emb = (const float*)d_in[3];
    const float* cls_tok = (const float*)d_in[4];
    const float* ln1_g   = (const float*)d_in[5];
    const float* ln1_b   = (const float*)d_in[6];
    const float* qkv_w   = (const float*)d_in[7];
    const float* scale   = (const float*)d_in[8];
    const float* out_w   = (const float*)d_in[9];
    const float* out_b   = (const float*)d_in[10];
    const float* ln2_g   = (const float*)d_in[11];
    const float* ln2_b   = (const float*)d_in[12];
    const float* ff_w1   = (const float*)d_in[13];
    const float* ff_b1   = (const float*)d_in[14];
    const float* ff_w2   = (const float*)d_in[15];
    const float* ff_b2   = (const float*)d_in[16];
    const float* lnf_g   = (const float*)d_in[17];
    const float* lnf_b   = (const float*)d_in[18];
    const float* head_w  = (const float*)d_in[19];
    const float* head_b  = (const float*)d_in[20];

    cudaFuncSetAttribute(hm_gemm, cudaFuncAttributeMaxDynamicSharedMemorySize, SMEM_DYN);

    float *xp;
    __half *qkvhp;
    __half *a2p, *a2hp, *a2op, *a2fp, *a2cp;
    __half *w2p, *w2q, *w2o, *w2f1, *w2f2, *w2h;
    cudaGetSymbolAddress((void**)&xp,    g_x);
    cudaGetSymbolAddress((void**)&qkvhp, g_qkvh);
    cudaGetSymbolAddress((void**)&a2p,  a2_patch);
    cudaGetSymbolAddress((void**)&a2hp, a2_h);
    cudaGetSymbolAddress((void**)&a2op, a2_o);
    cudaGetSymbolAddress((void**)&a2fp, a2_ff);
    cudaGetSymbolAddress((void**)&a2cp, a2_cls);
    cudaGetSymbolAddress((void**)&w2p,  w2_patch);
    cudaGetSymbolAddress((void**)&w2q,  w2_qkv);
    cudaGetSymbolAddress((void**)&w2o,  w2_out);
    cudaGetSymbolAddress((void**)&w2f1, w2_ff1);
    cudaGetSymbolAddress((void**)&w2f2, w2_ff2);
    cudaGetSymbolAddress((void**)&w2h,  w2_head);

    {
        int n = Bv * IMGv * IMGv;
        mean_kernel<<<(n + 255) / 256, 256>>>(img);
        int np = MP * PDv;
        patch_build_kernel<<<(np + 255) / 256, 256>>>(img);
        int nw = DIMv * PDv;
        convw_kernel<<<dim3((nw + 255) / 256, 1), 256>>>(patch_w, w2p, DIMv, PDv);
    }
    run_hm(a2p, w2p, patch_b, nullptr, pos_emb, xp, nullptr,
           MP, DIMv, K2_PD, FLAG_REMAP);
    cls_init_kernel<<<Bv, DIMv>>>(cls_tok, pos_emb);

    {
        int n;
        n = 3 * INNERv * DIMv;
        convw_kernel<<<dim3((n + 255) / 256, DEPTHv), 256>>>(qkv_w, w2q, 3 * INNERv, DIMv);
        n = DIMv * INNERv;
        convw_kernel<<<dim3((n + 255) / 256, DEPTHv), 256>>>(out_w, w2o, DIMv, INNERv);
        n = MLPv * DIMv;
        convw_kernel<<<dim3((n + 255) / 256, DEPTHv), 256>>>(ff_w1, w2f1, MLPv, DIMv);
        n = DIMv * MLPv;
        convw_kernel<<<dim3((n + 255) / 256, DEPTHv), 256>>>(ff_w2, w2f2, DIMv, MLPv);
        n = NCLSv * DIMv;
        convw_kernel<<<dim3((n + 255) / 256, 1), 256>>>(head_w, w2h, NCLSv, DIMv);
    }

    for (int L = 0; L < DEPTHv; L++) {
        ln_split_kernel<<<TOK, 128>>>(xp, ln1_g + L * DIMv, ln1_b + L * DIMv, a2hp, DIMv);
        run_hm(a2hp, w2q + (size_t)L * 3 * INNERv * K2_DIM, nullptr, nullptr, nullptr,
               nullptr, qkvhp, TOK, 3 * INNERv, K2_DIM, FLAG_HALF);
        attn4<<<Bv * Hv, 224>>>(scale + L * Hv);
        run_hm(a2op, w2o + (size_t)L * DIMv * K2_DIM, out_b + L * DIMv, xp, nullptr,
               xp, nullptr, TOK, DIMv, K2_DIM, 0);
        ln_split_kernel<<<TOK, 128>>>(xp, ln2_g + L * DIMv, ln2_b + L * DIMv, a2hp, DIMv);
        run_hm(a2hp, w2f1 + (size_t)L * MLPv * K2_DIM, ff_b1 + L * MLPv, nullptr, nullptr,
               nullptr, a2fp, TOK, MLPv, K2_DIM, FLAG_GELU | FLAG_SPLIT);
        run_hm(a2fp, w2f2 + (size_t)L * DIMv * K2_MLP, ff_b2 + L * DIMv, xp, nullptr,
               xp, nullptr, TOK, DIMv, K2_MLP, 0);
    }

    // final LN on cls rows (row b = x[b*197*384]) -> split, then head
    ln_split_kernel<<<Bv, 128>>>(xp, lnf_g, lnf_b, a2cp, (long)Nv * DIMv);
    run_hm(a2cp, w2h, head_b, nullptr, nullptr, (float*)d_out, nullptr,
           Bv, NCLSv, K2_DIM, 0);
}

// round 16
// speedup vs baseline: 1.4864x; 1.2682x over previous
#include <cuda_runtime.h>
#include <cuda_bf16.h>
#include <cuda_fp16.h>
#include <cstdint>
#include <cmath>

// ---------------- problem constants ----------------
#define Bv     64
#define Cv     3
#define IMGv   224
#define Pv     16
#define Sv     8
#define Gv     14
#define NPv    196
#define Nv     197
#define DIMv   384
#define DEPTHv 12
#define Hv     12
#define DHv    32
#define INNERv 384
#define MLPv   1536
#define NCLSv  1000
#define PDv    1792
#define TOK    (Bv*Nv)      // 12608
#define MP     (Bv*NPv)     // 12544
#define EPSv   1e-5f

#define K2_DIM (2*DIMv)     // 768
#define K2_PD  (2*PDv)      // 3584

// ---------------- scratch (device globals; no allocation allowed) ----------------
__device__ float g_mean [Bv * IMGv * IMGv];
__device__ float g_x    [TOK * DIMv];
__device__ float g_qkv  [TOK * 3 * INNERv];

__device__ __half a2_patch[(size_t)MP  * K2_PD];
__device__ __half a2_h    [(size_t)TOK * K2_DIM];    // 2-term LN output
__device__ __half a2_o    [(size_t)TOK * INNERv];    // single fp16 attention out
__device__ __half a2_ff   [(size_t)TOK * MLPv];      // single fp16 gelu out
__device__ __half a2_cls  [Bv * K2_DIM];

__device__ __half w2_patch[(size_t)DIMv  * K2_PD];
__device__ __half w2_qkv  [(size_t)DEPTHv * 3*INNERv * K2_DIM];
__device__ __half w1_out  [(size_t)DEPTHv * DIMv     * INNERv];  // single
__device__ __half w2_ff1  [(size_t)DEPTHv * MLPv     * K2_DIM];
__device__ __half w1_ff2  [(size_t)DEPTHv * DIMv     * MLPv];    // single
__device__ __half w2_head [(size_t)NCLSv * K2_DIM];

// ---------------- small helpers ----------------
__device__ __forceinline__ float gelu_exact(float x) {
    return 0.5f * x * (1.0f + erff(x * 0.70710678118654752440f));
}
__device__ __forceinline__ void split2h(float v, __half& hi, __half& lo) {
    hi = __float2half(v);
    lo = __float2half(v - __half2float(hi));
}
__device__ __forceinline__ uint32_t smem_u32(const void* p) {
    uint32_t a;
    asm("{ .reg .u64 t; cvta.to.shared.u64 t, %1; cvt.u32.u64 %0, t; }" : "=r"(a) : "l"(p));
    return a;
}
__device__ __forceinline__ void cp16(uint32_t dst, const void* src, uint32_t srcsize) {
    asm volatile("cp.async.cg.shared.global [%0], [%1], 16, %2;"
                 :: "r"(dst), "l"(src), "r"(srcsize) : "memory");
}
#define CP_COMMIT() asm volatile("cp.async.commit_group;" ::: "memory")
#define CP_WAIT2()  asm volatile("cp.async.wait_group 2;" ::: "memory")

__device__ __forceinline__ void ldsm4(uint32_t* r, uint32_t addr) {
    asm volatile("ldmatrix.sync.aligned.m8n8.x4.shared.b16 {%0,%1,%2,%3}, [%4];"
                 : "=r"(r[0]), "=r"(r[1]), "=r"(r[2]), "=r"(r[3]) : "r"(addr));
}
__device__ __forceinline__ void mma16816(float* c, const uint32_t* a,
                                         uint32_t b0, uint32_t b1) {
    asm volatile(
        "mma.sync.aligned.m16n8k16.row.col.f32.f16.f16.f32 "
        "{%0,%1,%2,%3}, {%4,%5,%6,%7}, {%8,%9}, {%0,%1,%2,%3};"
        : "+f"(c[0]), "+f"(c[1]), "+f"(c[2]), "+f"(c[3])
        : "r"(a[0]), "r"(a[1]), "r"(a[2]), "r"(a[3]), "r"(b0), "r"(b1));
}

// ---------------- preprocessing kernels ----------------
__global__ void mean_kernel(const float* __restrict__ img) {
    int idx = blockIdx.x * blockDim.x + threadIdx.x;
    if (idx >= Bv * IMGv * IMGv) return;
    int b = idx / (IMGv * IMGv);
    int yx = idx % (IMGv * IMGv);
    const float* p = img + (size_t)b * Cv * IMGv * IMGv + yx;
    g_mean[idx] = (p[0] + p[IMGv * IMGv] + p[2 * IMGv * IMGv]) * (1.0f / 3.0f);
}

__global__ void patch_build_kernel(const float* __restrict__ img) {
    int idx = blockIdx.x * blockDim.x + threadIdx.x;
    if (idx >= MP * PDv) return;
    int pd = idx % PDv;
    int n  = (idx / PDv) % NPv;
    int b  = idx / (PDv * NPv);
    int c  = pd % 7;
    int pp = pd / 7;
    int px = pp % Pv, py = pp / Pv;
    int gy = n / Gv, gx = n % Gv;
    int y = gy * Pv + py, x = gx * Pv + px;
    float v;
    if (c < 3) {
        v = img[(((size_t)b * Cv + c) * IMGv + y) * IMGv + x];
    } else {
        int yy = y, xx = x;
        if      (c == 3) xx = x - Sv;
        else if (c == 4) xx = x + Sv;
        else if (c == 5) yy = y - Sv;
        else             yy = y + Sv;
        v = (xx < 0 || xx >= IMGv || yy < 0 || yy >= IMGv)
                ? 0.0f : g_mean[((size_t)b * IMGv + yy) * IMGv + xx];
    }
    __half hi, lo; split2h(v, hi, lo);
    size_t row = (size_t)(b * NPv + n) * K2_PD;
    a2_patch[row + pd]       = hi;
    a2_patch[row + PDv + pd] = lo;
}

__global__ void cls_init_kernel(const float* __restrict__ cls_tok,
                                const float* __restrict__ pos) {
    int d = threadIdx.x;
    int b = blockIdx.x;
    g_x[(size_t)b * Nv * DIMv + d] = cls_tok[d] + pos[d];
}

// weight convert 2-term: src [L][Nr,K] fp32 -> dst [L][Nr,2K] fp16  ([hi|hi])
__global__ void convw_kernel(const float* __restrict__ src, __half* __restrict__ dst,
                             int Nr, int K) {
    int idx = blockIdx.x * 256 + threadIdx.x;
    if (idx >= Nr * K) return;
    src += (size_t)blockIdx.y * Nr * K;
    dst += (size_t)blockIdx.y * Nr * 2 * K;
    int n = idx / K, k = idx % K;
    __half hi = __float2half(src[idx]);
    size_t r = (size_t)n * 2 * K;
    dst[r + k]     = hi;
    dst[r + K + k] = hi;
}

// weight convert single: src [L][n] fp32 -> dst [L][n] fp16
__global__ void convw1_kernel(const float* __restrict__ src, __half* __restrict__ dst,
                              int n) {
    int idx = blockIdx.x * 256 + threadIdx.x;
    if (idx >= n) return;
    dst[(size_t)blockIdx.y * n + idx] =
        __float2half(src[(size_t)blockIdx.y * n + idx]);
}

// ---------------- layernorm -> split-fp16 activation ([hi|lo]) ----------------
__global__ void __launch_bounds__(128)
ln_split_kernel(const float* __restrict__ x, const float* __restrict__ g,
                const float* __restrict__ bta, __half* __restrict__ out,
                long in_stride)
{
    long r = blockIdx.x;
    const float* xr = x + r * in_stride;
    int t = threadIdx.x;
    float v0 = xr[t], v1 = xr[t + 128], v2 = xr[t + 256];
    float s1 = v0 + v1 + v2;
    float s2 = v0 * v0 + v1 * v1 + v2 * v2;
    #pragma unroll
    for (int o = 16; o; o >>= 1) {
        s1 += __shfl_xor_sync(0xFFFFFFFFu, s1, o);
        s2 += __shfl_xor_sync(0xFFFFFFFFu, s2, o);
    }
    __shared__ float sh[8];
    int w = t >> 5;
    if ((t & 31) == 0) { sh[w] = s1; sh[4 + w] = s2; }
    __syncthreads();
    s1 = sh[0] + sh[1] + sh[2] + sh[3];
    s2 = sh[4] + sh[5] + sh[6] + sh[7];
    float mu  = s1 * (1.0f / DIMv);
    float var = s2 * (1.0f / DIMv) - mu * mu;
    float rs  = rsqrtf(var + EPSv);
    __half* orow = out + r * (long)K2_DIM;
    #pragma unroll
    for (int q = 0; q < 3; q++) {
        int c = t + q * 128;
        float vv = (q == 0 ? v0 : (q == 1 ? v1 : v2));
        float y = (vv - mu) * rs * g[c] + bta[c];
        __half hi, lo; split2h(y, hi, lo);
        orow[c]        = hi;
        orow[DIMv + c] = lo;
    }
}

// ---------------- attention v3 (R12): fp32 qkv; writes single fp16 o ----------------
__global__ void __launch_bounds__(224)
attn3(const float* __restrict__ scale)
{
    __shared__ float4 Ks[Nv][8];
    __shared__ float4 Vs[Nv][8];
    int h = blockIdx.x % Hv;
    int b = blockIdx.x / Hv;
    const float* base = g_qkv + (size_t)b * Nv * (3 * INNERv) + h * DHv;

    for (int idx = threadIdx.x; idx < Nv * 8; idx += 224) {
        int r = idx >> 3;
        int c = idx & 7;
        const float* row = base + (size_t)r * (3 * INNERv);
        Ks[r][c] = *(const float4*)(row + INNERv + c * 4);
        Vs[r][c] = *(const float4*)(row + 2 * INNERv + c * 4);
    }
    __syncthreads();

    int i = threadIdx.x;
    if (i >= Nv) return;
    float sc = scale[h];
    const float* qrow = base + (size_t)i * (3 * INNERv);
    float4 q[8];
    #pragma unroll
    for (int c = 0; c < 8; c++) {
        float4 v = *(const float4*)(qrow + c * 4);
        q[c] = make_float4(v.x * sc, v.y * sc, v.z * sc, v.w * sc);
    }

    float s = 0.0f;
    float4 acc[8];
    #pragma unroll
    for (int c = 0; c < 8; c++) acc[c] = make_float4(0.f, 0.f, 0.f, 0.f);

    #pragma unroll 2
    for (int j = 0; j < Nv; j++) {
        float d0 = 0.f, d1 = 0.f, d2 = 0.f, d3 = 0.f;
        #pragma unroll
        for (int c = 0; c < 8; c++) {
            float4 k = Ks[j][c];
            d0 = fmaf(q[c].x, k.x, d0);
            d1 = fmaf(q[c].y, k.y, d1);
            d2 = fmaf(q[c].z, k.z, d2);
            d3 = fmaf(q[c].w, k.w, d3);
        }
        float d = (d0 + d1) + (d2 + d3);
        float p = (j == i) ? 0.0f : __expf(d);
        s += p;
        #pragma unroll
        for (int c = 0; c < 8; c++) {
            float4 v = Vs[j][c];
            acc[c].x = fmaf(p, v.x, acc[c].x);
            acc[c].y = fmaf(p, v.y, acc[c].y);
            acc[c].z = fmaf(p, v.z, acc[c].z);
            acc[c].w = fmaf(p, v.w, acc[c].w);
        }
    }

    float inv = 1.0f / s;
    __half* o = a2_o + (size_t)(b * Nv + i) * INNERv + h * DHv;
    #pragma unroll
    for (int c = 0; c < 8; c++) {
        *(__half2*)(o + c * 4) =
            __halves2half2(__float2half(acc[c].x * inv), __float2half(acc[c].y * inv));
        *(__half2*)(o + c * 4 + 2) =
            __halves2half2(__float2half(acc[c].z * inv), __float2half(acc[c].w * inv));
    }
}

// ---------------- HMMA fp16 GEMM: C = A[M,K] * W[N,K]^T ----------------
// R12 config: CTA 128x128, 8 warps of 64x32, BK=32, 4-stage ring, single sync.
#define FLAG_GELU  1
#define FLAG_REMAP 2
#define FLAG_HALF  8
#define HSTRIDE 40                       // halves per smem row (80B, conflict-free)
#define HS_B    (128 * HSTRIDE * 2)      // 10240B
#define STAGEB  (2 * 128 * HSTRIDE * 2)  // 20480B
#define NSTAGE  4
#define SMEM_DYN (NSTAGE * STAGEB)       // 81920B

__device__ __forceinline__ void store_pair(
    float v0, float v1, int orow, int gn, int Nn,
    const float* bias, const float* resid, const float* pos,
    float* Cf, __half* Cs, int flags)
{
    if (bias) { v0 += bias[gn]; v1 += bias[gn + 1]; }
    if (flags & FLAG_GELU) { v0 = gelu_exact(v0); v1 = gelu_exact(v1); }
    if (pos) {
        const float* pp = pos + (size_t)(orow % Nv) * Nn + gn;
        v0 += pp[0]; v1 += pp[1];
    }
    if (resid) {
        const float* rr = resid + (size_t)orow * Nn + gn;
        v0 += rr[0]; v1 += rr[1];
    }
    if (flags & FLAG_HALF) {
        *(__half2*)(Cs + (size_t)orow * Nn + gn) =
            __halves2half2(__float2half(v0), __float2half(v1));
    } else {
        *(float2*)(Cf + (size_t)orow * Nn + gn) = make_float2(v0, v1);
    }
}

__global__ void __launch_bounds__(256, 2)
hm_gemm(const __half* __restrict__ A, const __half* __restrict__ W,
        const float* __restrict__ bias, const float* __restrict__ resid,
        const float* __restrict__ pos, float* __restrict__ Cf,
        __half* __restrict__ Cs,
        int M, int Nn, int K2, int flags)
{
    extern __shared__ __align__(16) char sm[];
    uint32_t sbase = smem_u32(sm);
    int tid = threadIdx.x, lane = tid & 31, wid = tid >> 5;
    int m0 = blockIdx.y * 128, n0 = blockIdx.x * 128;
    int wr = wid >> 2, wc = wid & 3;     // warp tile: 64(M) x 32(N)

    float c[4][4][4];
    #pragma unroll
    for (int i = 0; i < 4; i++)
        #pragma unroll
        for (int j = 0; j < 4; j++)
            #pragma unroll
            for (int q = 0; q < 4; q++) c[i][j][q] = 0.0f;

    const int rbase = tid >> 2;          // 0..63
    const int kseg  = (tid & 3) * 8;     // halves

    const int nk = K2 / 32;

    auto load_stage = [&](int slot, int ch) {
        uint32_t sa = sbase + slot * STAGEB;
        int kk = ch * 32;
        #pragma unroll
        for (int i = 0; i < 2; i++) {
            int r = rbase + i * 64;
            uint32_t dst = sa + (uint32_t)(r * HSTRIDE + kseg) * 2;
            const void* src = A + (size_t)(m0 + r) * K2 + kk + kseg;
            cp16(dst, src, (m0 + r < M) ? 16u : 0u);
        }
        #pragma unroll
        for (int i = 0; i < 2; i++) {
            int r = rbase + i * 64;
            uint32_t dst = sa + HS_B + (uint32_t)(r * HSTRIDE + kseg) * 2;
            const void* src = W + (size_t)(n0 + r) * K2 + kk + kseg;
            cp16(dst, src, (n0 + r < Nn) ? 16u : 0u);
        }
        CP_COMMIT();
    };

    #pragma unroll
    for (int s = 0; s < NSTAGE - 1; s++) load_stage(s, s);   // nk >= 3 always

    for (int ch = 0; ch < nk; ch++) {
        CP_WAIT2();
        __syncthreads();
        if (ch + NSTAGE - 1 < nk) load_stage((ch + NSTAGE - 1) & 3, ch + NSTAGE - 1);
        else CP_COMMIT();

        uint32_t sa = sbase + (ch & 3) * STAGEB;
        #pragma unroll
        for (int ko = 0; ko < 2; ko++) {
            int col = ko * 16 + ((lane >> 4) << 3);
            uint32_t a[4][4];
            #pragma unroll
            for (int mf = 0; mf < 4; mf++) {
                int row = wr * 64 + mf * 16 + (lane & 15);
                ldsm4(a[mf], sa + (uint32_t)(row * HSTRIDE + col) * 2);
            }
            uint32_t b[2][4];
            #pragma unroll
            for (int p = 0; p < 2; p++) {
                int row = wc * 32 + p * 16 + (lane & 15);
                ldsm4(b[p], sa + HS_B + (uint32_t)(row * HSTRIDE + col) * 2);
            }
            #pragma unroll
            for (int mf = 0; mf < 4; mf++)
                #pragma unroll
                for (int nf = 0; nf < 4; nf++) {
                    int p = nf >> 1, q = nf & 1;
                    mma16816(c[mf][nf], a[mf], b[p][q], b[p][2 + q]);
                }
        }
    }

    // ---- epilogue ----
    #pragma unroll
    for (int mf = 0; mf < 4; mf++) {
        int r0 = m0 + wr * 64 + mf * 16 + (lane >> 2);
        #pragma unroll
        for (int nf = 0; nf < 4; nf++) {
            int gn = n0 + wc * 32 + nf * 8 + (lane & 3) * 2;
            if (gn >= Nn) continue;
            if (r0 < M) {
                int orow = r0;
                if (flags & FLAG_REMAP) { int b = r0 / NPv; orow = r0 + b + 1; }
                store_pair(c[mf][nf][0], c[mf][nf][1], orow, gn, Nn,
                           bias, resid, pos, Cf, Cs, flags);
            }
            int r1 = r0 + 8;
            if (r1 < M) {
                int orow = r1;
                if (flags & FLAG_REMAP) { int b = r1 / NPv; orow = r1 + b + 1; }
                store_pair(c[mf][nf][2], c[mf][nf][3], orow, gn, Nn,
                           bias, resid, pos, Cf, Cs, flags);
            }
        }
    }
}

// ---------------- host side ----------------
static inline void run_hm(const __half* A, const __half* W,
                          const float* bias, const float* resid, const float* pos,
                          float* Cf, __half* Cs,
                          int M, int Nn, int K2, int flags)
{
    dim3 grid((Nn + 127) / 128, (M + 127) / 128);
    hm_gemm<<<grid, 256, SMEM_DYN>>>(A, W, bias, resid, pos, Cf, Cs, M, Nn, K2, flags);
}

extern "C" void kernel_launch(void* const* d_in, const int* in_sizes, int n_in,
                              void* d_out, int out_size)
{
    const float* img     = (const float*)d_in[0];
    const float* patch_w = (const float*)d_in[1];
    const float* patch_b = (const float*)d_in[2];
    const float* pos_emb = (const float*)d_in[3];
    const float* cls_tok = (const float*)d_in[4];
    const float* ln1_g   = (const float*)d_in[5];
    const float* ln1_b   = (const float*)d_in[6];
    const float* qkv_w   = (const float*)d_in[7];
    const float* scale   = (const float*)d_in[8];
    const float* out_w   = (const float*)d_in[9];
    const float* out_b   = (const float*)d_in[10];
    const float* ln2_g   = (const float*)d_in[11];
    const float* ln2_b   = (const float*)d_in[12];
    const float* ff_w1   = (const float*)d_in[13];
    const float* ff_b1   = (const float*)d_in[14];
    const float* ff_w2   = (const float*)d_in[15];
    const float* ff_b2   = (const float*)d_in[16];
    const float* lnf_g   = (const float*)d_in[17];
    const float* lnf_b   = (const float*)d_in[18];
    const float* head_w  = (const float*)d_in[19];
    const float* head_b  = (const float*)d_in[20];

    cudaFuncSetAttribute(hm_gemm, cudaFuncAttributeMaxDynamicSharedMemorySize, SMEM_DYN);

    float *xp, *qkvp;
    __half *a2p, *a2hp, *a2op, *a2fp, *a2cp;
    __half *w2p, *w2q, *w1o, *w2f1, *w1f2, *w2h;
    cudaGetSymbolAddress((void**)&xp,   g_x);
    cudaGetSymbolAddress((void**)&qkvp, g_qkv);
    cudaGetSymbolAddress((void**)&a2p,  a2_patch);
    cudaGetSymbolAddress((void**)&a2hp, a2_h);
    cudaGetSymbolAddress((void**)&a2op, a2_o);
    cudaGetSymbolAddress((void**)&a2fp, a2_ff);
    cudaGetSymbolAddress((void**)&a2cp, a2_cls);
    cudaGetSymbolAddress((void**)&w2p,  w2_patch);
    cudaGetSymbolAddress((void**)&w2q,  w2_qkv);
    cudaGetSymbolAddress((void**)&w1o,  w1_out);
    cudaGetSymbolAddress((void**)&w2f1, w2_ff1);
    cudaGetSymbolAddress((void**)&w1f2, w1_ff2);
    cudaGetSymbolAddress((void**)&w2h,  w2_head);

    {
        int n = Bv * IMGv * IMGv;
        mean_kernel<<<(n + 255) / 256, 256>>>(img);
        int np = MP * PDv;
        patch_build_kernel<<<(np + 255) / 256, 256>>>(img);
        int nw = DIMv * PDv;
        convw_kernel<<<dim3((nw + 255) / 256, 1), 256>>>(patch_w, w2p, DIMv, PDv);
    }
    run_hm(a2p, w2p, patch_b, nullptr, pos_emb, xp, nullptr,
           MP, DIMv, K2_PD, FLAG_REMAP);
    cls_init_kernel<<<Bv, DIMv>>>(cls_tok, pos_emb);

    {
        int n;
        n = 3 * INNERv * DIMv;
        convw_kernel<<<dim3((n + 255) / 256, DEPTHv), 256>>>(qkv_w, w2q, 3 * INNERv, DIMv);
        n = DIMv * INNERv;
        convw1_kernel<<<dim3((n + 255) / 256, DEPTHv), 256>>>(out_w, w1o, n);
        n = MLPv * DIMv;
        convw_kernel<<<dim3((n + 255) / 256, DEPTHv), 256>>>(ff_w1, w2f1, MLPv, DIMv);
        n = DIMv * MLPv;
        convw1_kernel<<<dim3((n + 255) / 256, DEPTHv), 256>>>(ff_w2, w1f2, n);
        n = NCLSv * DIMv;
        convw_kernel<<<dim3((n + 255) / 256, 1), 256>>>(head_w, w2h, NCLSv, DIMv);
    }

    for (int L = 0; L < DEPTHv; L++) {
        ln_split_kernel<<<TOK, 128>>>(xp, ln1_g + L * DIMv, ln1_b + L * DIMv, a2hp, DIMv);
        run_hm(a2hp, w2q + (size_t)L * 3 * INNERv * K2_DIM, nullptr, nullptr, nullptr,
               qkvp, nullptr, TOK, 3 * INNERv, K2_DIM, 0);
        attn3<<<Bv * Hv, 224>>>(scale + L * Hv);
        run_hm(a2op, w1o + (size_t)L * DIMv * INNERv, out_b + L * DIMv, xp, nullptr,
               xp, nullptr, TOK, DIMv, INNERv, 0);
        ln_split_kernel<<<TOK, 128>>>(xp, ln2_g + L * DIMv, ln2_b + L * DIMv, a2hp, DIMv);
        run_hm(a2hp, w2f1 + (size_t)L * MLPv * K2_DIM, ff_b1 + L * MLPv, nullptr, nullptr,
               nullptr, a2fp, TOK, MLPv, K2_DIM, FLAG_GELU | FLAG_HALF);
        run_hm(a2fp, w1f2 + (size_t)L * DIMv * MLPv, ff_b2 + L * DIMv, xp, nullptr,
               xp, nullptr, TOK, DIMv, MLPv, 0);
    }

    // final LN on cls rows (row b = x[b*197*384]) -> split, then head
    ln_split_kernel<<<Bv, 128>>>(xp, lnf_g, lnf_b, a2cp, (long)Nv * DIMv);
    run_hm(a2cp, w2h, head_b, nullptr, nullptr, (float*)d_out, nullptr,
           Bv, NCLSv, K2_DIM, 0);
}

// round 17
// speedup vs baseline: 1.7616x; 1.1852x over previous
#include <cuda_runtime.h>
#include <cuda_bf16.h>
#include <cuda_fp16.h>
#include <cstdint>
#include <cmath>

// ---------------- problem constants ----------------
#define Bv     64
#define Cv     3
#define IMGv   224
#define Pv     16
#define Sv     8
#define Gv     14
#define NPv    196
#define Nv     197
#define DIMv   384
#define DEPTHv 12
#define Hv     12
#define DHv    32
#define INNERv 384
#define MLPv   1536
#define NCLSv  1000
#define PDv    1792
#define TOK    (Bv*Nv)      // 12608
#define MP     (Bv*NPv)     // 12544
#define EPSv   1e-5f

#define K2_DIM (2*DIMv)     // 768
#define K2_PD  (2*PDv)      // 3584

// ---------------- scratch (device globals; no allocation allowed) ----------------
__device__ float g_mean [Bv * IMGv * IMGv];
__device__ float g_x    [TOK * DIMv];
__device__ float g_qkv  [TOK * 3 * INNERv];

__device__ __half a2_patch[(size_t)MP  * K2_PD];
__device__ __half a2_h    [(size_t)TOK * DIMv];      // single fp16 LN output
__device__ __half a2_o    [(size_t)TOK * INNERv];    // single fp16 attention out
__device__ __half a2_ff   [(size_t)TOK * MLPv];      // single fp16 gelu out
__device__ __half a2_cls  [Bv * K2_DIM];             // 2-term for head

__device__ __half w2_patch[(size_t)DIMv  * K2_PD];
__device__ __half w1_qkv  [(size_t)DEPTHv * 3*INNERv * DIMv];   // single
__device__ __half w1_out  [(size_t)DEPTHv * DIMv     * INNERv]; // single
__device__ __half w1_ff1  [(size_t)DEPTHv * MLPv     * DIMv];   // single
__device__ __half w1_ff2  [(size_t)DEPTHv * DIMv     * MLPv];   // single
__device__ __half w2_head [(size_t)NCLSv * K2_DIM];

// ---------------- small helpers ----------------
__device__ __forceinline__ float gelu_exact(float x) {
    return 0.5f * x * (1.0f + erff(x * 0.70710678118654752440f));
}
__device__ __forceinline__ void split2h(float v, __half& hi, __half& lo) {
    hi = __float2half(v);
    lo = __float2half(v - __half2float(hi));
}
__device__ __forceinline__ uint32_t smem_u32(const void* p) {
    uint32_t a;
    asm("{ .reg .u64 t; cvta.to.shared.u64 t, %1; cvt.u32.u64 %0, t; }" : "=r"(a) : "l"(p));
    return a;
}
__device__ __forceinline__ void cp16(uint32_t dst, const void* src, uint32_t srcsize) {
    asm volatile("cp.async.cg.shared.global [%0], [%1], 16, %2;"
                 :: "r"(dst), "l"(src), "r"(srcsize) : "memory");
}
#define CP_COMMIT() asm volatile("cp.async.commit_group;" ::: "memory")
#define CP_WAIT2()  asm volatile("cp.async.wait_group 2;" ::: "memory")

__device__ __forceinline__ void ldsm4(uint32_t* r, uint32_t addr) {
    asm volatile("ldmatrix.sync.aligned.m8n8.x4.shared.b16 {%0,%1,%2,%3}, [%4];"
                 : "=r"(r[0]), "=r"(r[1]), "=r"(r[2]), "=r"(r[3]) : "r"(addr));
}
__device__ __forceinline__ void mma16816(float* c, const uint32_t* a,
                                         uint32_t b0, uint32_t b1) {
    asm volatile(
        "mma.sync.aligned.m16n8k16.row.col.f32.f16.f16.f32 "
        "{%0,%1,%2,%3}, {%4,%5,%6,%7}, {%8,%9}, {%0,%1,%2,%3};"
        : "+f"(c[0]), "+f"(c[1]), "+f"(c[2]), "+f"(c[3])
        : "r"(a[0]), "r"(a[1]), "r"(a[2]), "r"(a[3]), "r"(b0), "r"(b1));
}

// ---------------- preprocessing kernels ----------------
__global__ void mean_kernel(const float* __restrict__ img) {
    int idx = blockIdx.x * blockDim.x + threadIdx.x;
    if (idx >= Bv * IMGv * IMGv) return;
    int b = idx / (IMGv * IMGv);
    int yx = idx % (IMGv * IMGv);
    const float* p = img + (size_t)b * Cv * IMGv * IMGv + yx;
    g_mean[idx] = (p[0] + p[IMGv * IMGv] + p[2 * IMGv * IMGv]) * (1.0f / 3.0f);
}

__global__ void patch_build_kernel(const float* __restrict__ img) {
    int idx = blockIdx.x * blockDim.x + threadIdx.x;
    if (idx >= MP * PDv) return;
    int pd = idx % PDv;
    int n  = (idx / PDv) % NPv;
    int b  = idx / (PDv * NPv);
    int c  = pd % 7;
    int pp = pd / 7;
    int px = pp % Pv, py = pp / Pv;
    int gy = n / Gv, gx = n % Gv;
    int y = gy * Pv + py, x = gx * Pv + px;
    float v;
    if (c < 3) {
        v = img[(((size_t)b * Cv + c) * IMGv + y) * IMGv + x];
    } else {
        int yy = y, xx = x;
        if      (c == 3) xx = x - Sv;
        else if (c == 4) xx = x + Sv;
        else if (c == 5) yy = y - Sv;
        else             yy = y + Sv;
        v = (xx < 0 || xx >= IMGv || yy < 0 || yy >= IMGv)
                ? 0.0f : g_mean[((size_t)b * IMGv + yy) * IMGv + xx];
    }
    __half hi, lo; split2h(v, hi, lo);
    size_t row = (size_t)(b * NPv + n) * K2_PD;
    a2_patch[row + pd]       = hi;
    a2_patch[row + PDv + pd] = lo;
}

__global__ void cls_init_kernel(const float* __restrict__ cls_tok,
                                const float* __restrict__ pos) {
    int d = threadIdx.x;
    int b = blockIdx.x;
    g_x[(size_t)b * Nv * DIMv + d] = cls_tok[d] + pos[d];
}

// weight convert 2-term: src [L][Nr,K] fp32 -> dst [L][Nr,2K] fp16  ([hi|hi])
__global__ void convw_kernel(const float* __restrict__ src, __half* __restrict__ dst,
                             int Nr, int K) {
    int idx = blockIdx.x * 256 + threadIdx.x;
    if (idx >= Nr * K) return;
    src += (size_t)blockIdx.y * Nr * K;
    dst += (size_t)blockIdx.y * Nr * 2 * K;
    int n = idx / K, k = idx % K;
    __half hi = __float2half(src[idx]);
    size_t r = (size_t)n * 2 * K;
    dst[r + k]     = hi;
    dst[r + K + k] = hi;
}

// weight convert single: src [L][n] fp32 -> dst [L][n] fp16
__global__ void convw1_kernel(const float* __restrict__ src, __half* __restrict__ dst,
                              int n) {
    int idx = blockIdx.x * 256 + threadIdx.x;
    if (idx >= n) return;
    dst[(size_t)blockIdx.y * n + idx] =
        __float2half(src[(size_t)blockIdx.y * n + idx]);
}

// ---------------- layernorm -> fp16 ([hi] or [hi|lo]) ----------------
__global__ void __launch_bounds__(128)
ln_split_kernel(const float* __restrict__ x, const float* __restrict__ g,
                const float* __restrict__ bta, __half* __restrict__ out,
                long in_stride, int two_term)
{
    long r = blockIdx.x;
    const float* xr = x + r * in_stride;
    int t = threadIdx.x;
    float v0 = xr[t], v1 = xr[t + 128], v2 = xr[t + 256];
    float s1 = v0 + v1 + v2;
    float s2 = v0 * v0 + v1 * v1 + v2 * v2;
    #pragma unroll
    for (int o = 16; o; o >>= 1) {
        s1 += __shfl_xor_sync(0xFFFFFFFFu, s1, o);
        s2 += __shfl_xor_sync(0xFFFFFFFFu, s2, o);
    }
    __shared__ float sh[8];
    int w = t >> 5;
    if ((t & 31) == 0) { sh[w] = s1; sh[4 + w] = s2; }
    __syncthreads();
    s1 = sh[0] + sh[1] + sh[2] + sh[3];
    s2 = sh[4] + sh[5] + sh[6] + sh[7];
    float mu  = s1 * (1.0f / DIMv);
    float var = s2 * (1.0f / DIMv) - mu * mu;
    float rs  = rsqrtf(var + EPSv);
    long ostride = two_term ? (long)K2_DIM : (long)DIMv;
    __half* orow = out + r * ostride;
    #pragma unroll
    for (int q = 0; q < 3; q++) {
        int c = t + q * 128;
        float vv = (q == 0 ? v0 : (q == 1 ? v1 : v2));
        float y = (vv - mu) * rs * g[c] + bta[c];
        if (two_term) {
            __half hi, lo; split2h(y, hi, lo);
            orow[c]        = hi;
            orow[DIMv + c] = lo;
        } else {
            orow[c] = __float2half(y);
        }
    }
}

// ---------------- attention: fp32 qkv; writes single fp16 o ----------------
__global__ void __launch_bounds__(224)
attn3(const float* __restrict__ scale)
{
    __shared__ float4 Ks[Nv][8];
    __shared__ float4 Vs[Nv][8];
    int h = blockIdx.x % Hv;
    int b = blockIdx.x / Hv;
    const float* base = g_qkv + (size_t)b * Nv * (3 * INNERv) + h * DHv;

    for (int idx = threadIdx.x; idx < Nv * 8; idx += 224) {
        int r = idx >> 3;
        int c = idx & 7;
        const float* row = base + (size_t)r * (3 * INNERv);
        Ks[r][c] = *(const float4*)(row + INNERv + c * 4);
        Vs[r][c] = *(const float4*)(row + 2 * INNERv + c * 4);
    }
    __syncthreads();

    int i = threadIdx.x;
    if (i >= Nv) return;
    float sc = scale[h];
    const float* qrow = base + (size_t)i * (3 * INNERv);
    float4 q[8];
    #pragma unroll
    for (int c = 0; c < 8; c++) {
        float4 v = *(const float4*)(qrow + c * 4);
        q[c] = make_float4(v.x * sc, v.y * sc, v.z * sc, v.w * sc);
    }

    float s = 0.0f;
    float4 acc[8];
    #pragma unroll
    for (int c = 0; c < 8; c++) acc[c] = make_float4(0.f, 0.f, 0.f, 0.f);

    #pragma unroll 2
    for (int j = 0; j < Nv; j++) {
        float d0 = 0.f, d1 = 0.f, d2 = 0.f, d3 = 0.f;
        #pragma unroll
        for (int c = 0; c < 8; c++) {
            float4 k = Ks[j][c];
            d0 = fmaf(q[c].x, k.x, d0);
            d1 = fmaf(q[c].y, k.y, d1);
            d2 = fmaf(q[c].z, k.z, d2);
            d3 = fmaf(q[c].w, k.w, d3);
        }
        float d = (d0 + d1) + (d2 + d3);
        float p = (j == i) ? 0.0f : __expf(d);
        s += p;
        #pragma unroll
        for (int c = 0; c < 8; c++) {
            float4 v = Vs[j][c];
            acc[c].x = fmaf(p, v.x, acc[c].x);
            acc[c].y = fmaf(p, v.y, acc[c].y);
            acc[c].z = fmaf(p, v.z, acc[c].z);
            acc[c].w = fmaf(p, v.w, acc[c].w);
        }
    }

    float inv = 1.0f / s;
    __half* o = a2_o + (size_t)(b * Nv + i) * INNERv + h * DHv;
    #pragma unroll
    for (int c = 0; c < 8; c++) {
        *(__half2*)(o + c * 4) =
            __halves2half2(__float2half(acc[c].x * inv), __float2half(acc[c].y * inv));
        *(__half2*)(o + c * 4 + 2) =
            __halves2half2(__float2half(acc[c].z * inv), __float2half(acc[c].w * inv));
    }
}

// ---------------- HMMA fp16 GEMM: C = A[M,K] * W[N,K]^T ----------------
// R12 config: CTA 128x128, 8 warps of 64x32, BK=32, 4-stage ring, single sync.
#define FLAG_GELU  1
#define FLAG_REMAP 2
#define FLAG_HALF  8
#define HSTRIDE 40                       // halves per smem row (80B, conflict-free)
#define HS_B    (128 * HSTRIDE * 2)      // 10240B
#define STAGEB  (2 * 128 * HSTRIDE * 2)  // 20480B
#define NSTAGE  4
#define SMEM_DYN (NSTAGE * STAGEB)       // 81920B

__device__ __forceinline__ void store_pair(
    float v0, float v1, int orow, int gn, int Nn,
    const float* bias, const float* resid, const float* pos,
    float* Cf, __half* Cs, int flags)
{
    if (bias) { v0 += bias[gn]; v1 += bias[gn + 1]; }
    if (flags & FLAG_GELU) { v0 = gelu_exact(v0); v1 = gelu_exact(v1); }
    if (pos) {
        const float* pp = pos + (size_t)(orow % Nv) * Nn + gn;
        v0 += pp[0]; v1 += pp[1];
    }
    if (resid) {
        const float* rr = resid + (size_t)orow * Nn + gn;
        v0 += rr[0]; v1 += rr[1];
    }
    if (flags & FLAG_HALF) {
        *(__half2*)(Cs + (size_t)orow * Nn + gn) =
            __halves2half2(__float2half(v0), __float2half(v1));
    } else {
        *(float2*)(Cf + (size_t)orow * Nn + gn) = make_float2(v0, v1);
    }
}

__global__ void __launch_bounds__(256, 2)
hm_gemm(const __half* __restrict__ A, const __half* __restrict__ W,
        const float* __restrict__ bias, const float* __restrict__ resid,
        const float* __restrict__ pos, float* __restrict__ Cf,
        __half* __restrict__ Cs,
        int M, int Nn, int K2, int flags)
{
    extern __shared__ __align__(16) char sm[];
    uint32_t sbase = smem_u32(sm);
    int tid = threadIdx.x, lane = tid & 31, wid = tid >> 5;
    int m0 = blockIdx.y * 128, n0 = blockIdx.x * 128;
    int wr = wid >> 2, wc = wid & 3;     // warp tile: 64(M) x 32(N)

    float c[4][4][4];
    #pragma unroll
    for (int i = 0; i < 4; i++)
        #pragma unroll
        for (int j = 0; j < 4; j++)
            #pragma unroll
            for (int q = 0; q < 4; q++) c[i][j][q] = 0.0f;

    const int rbase = tid >> 2;          // 0..63
    const int kseg  = (tid & 3) * 8;     // halves

    const int nk = K2 / 32;

    auto load_stage = [&](int slot, int ch) {
        uint32_t sa = sbase + slot * STAGEB;
        int kk = ch * 32;
        #pragma unroll
        for (int i = 0; i < 2; i++) {
            int r = rbase + i * 64;
            uint32_t dst = sa + (uint32_t)(r * HSTRIDE + kseg) * 2;
            const void* src = A + (size_t)(m0 + r) * K2 + kk + kseg;
            cp16(dst, src, (m0 + r < M) ? 16u : 0u);
        }
        #pragma unroll
        for (int i = 0; i < 2; i++) {
            int r = rbase + i * 64;
            uint32_t dst = sa + HS_B + (uint32_t)(r * HSTRIDE + kseg) * 2;
            const void* src = W + (size_t)(n0 + r) * K2 + kk + kseg;
            cp16(dst, src, (n0 + r < Nn) ? 16u : 0u);
        }
        CP_COMMIT();
    };

    #pragma unroll
    for (int s = 0; s < NSTAGE - 1; s++) load_stage(s, s);   // nk >= 3 always

    for (int ch = 0; ch < nk; ch++) {
        CP_WAIT2();
        __syncthreads();
        if (ch + NSTAGE - 1 < nk) load_stage((ch + NSTAGE - 1) & 3, ch + NSTAGE - 1);
        else CP_COMMIT();

        uint32_t sa = sbase + (ch & 3) * STAGEB;
        #pragma unroll
        for (int ko = 0; ko < 2; ko++) {
            int col = ko * 16 + ((lane >> 4) << 3);
            uint32_t a[4][4];
            #pragma unroll
            for (int mf = 0; mf < 4; mf++) {
                int row = wr * 64 + mf * 16 + (lane & 15);
                ldsm4(a[mf], sa + (uint32_t)(row * HSTRIDE + col) * 2);
            }
            uint32_t b[2][4];
            #pragma unroll
            for (int p = 0; p < 2; p++) {
                int row = wc * 32 + p * 16 + (lane & 15);
                ldsm4(b[p], sa + HS_B + (uint32_t)(row * HSTRIDE + col) * 2);
            }
            #pragma unroll
            for (int mf = 0; mf < 4; mf++)
                #pragma unroll
                for (int nf = 0; nf < 4; nf++) {
                    int p = nf >> 1, q = nf & 1;
                    mma16816(c[mf][nf], a[mf], b[p][q], b[p][2 + q]);
                }
        }
    }

    // ---- epilogue ----
    #pragma unroll
    for (int mf = 0; mf < 4; mf++) {
        int r0 = m0 + wr * 64 + mf * 16 + (lane >> 2);
        #pragma unroll
        for (int nf = 0; nf < 4; nf++) {
            int gn = n0 + wc * 32 + nf * 8 + (lane & 3) * 2;
            if (gn >= Nn) continue;
            if (r0 < M) {
                int orow = r0;
                if (flags & FLAG_REMAP) { int b = r0 / NPv; orow = r0 + b + 1; }
                store_pair(c[mf][nf][0], c[mf][nf][1], orow, gn, Nn,
                           bias, resid, pos, Cf, Cs, flags);
            }
            int r1 = r0 + 8;
            if (r1 < M) {
                int orow = r1;
                if (flags & FLAG_REMAP) { int b = r1 / NPv; orow = r1 + b + 1; }
                store_pair(c[mf][nf][2], c[mf][nf][3], orow, gn, Nn,
                           bias, resid, pos, Cf, Cs, flags);
            }
        }
    }
}

// ---------------- host side ----------------
static inline void run_hm(const __half* A, const __half* W,
                          const float* bias, const float* resid, const float* pos,
                          float* Cf, __half* Cs,
                          int M, int Nn, int K2, int flags)
{
    dim3 grid((Nn + 127) / 128, (M + 127) / 128);
    hm_gemm<<<grid, 256, SMEM_DYN>>>(A, W, bias, resid, pos, Cf, Cs, M, Nn, K2, flags);
}

extern "C" void kernel_launch(void* const* d_in, const int* in_sizes, int n_in,
                              void* d_out, int out_size)
{
    const float* img     = (const float*)d_in[0];
    const float* patch_w = (const float*)d_in[1];
    const float* patch_b = (const float*)d_in[2];
    const float* pos_emb = (const float*)d_in[3];
    const float* cls_tok = (const float*)d_in[4];
    const float* ln1_g   = (const float*)d_in[5];
    const float* ln1_b   = (const float*)d_in[6];
    const float* qkv_w   = (const float*)d_in[7];
    const float* scale   = (const float*)d_in[8];
    const float* out_w   = (const float*)d_in[9];
    const float* out_b   = (const float*)d_in[10];
    const float* ln2_g   = (const float*)d_in[11];
    const float* ln2_b   = (const float*)d_in[12];
    const float* ff_w1   = (const float*)d_in[13];
    const float* ff_b1   = (const float*)d_in[14];
    const float* ff_w2   = (const float*)d_in[15];
    const float* ff_b2   = (const float*)d_in[16];
    const float* lnf_g   = (const float*)d_in[17];
    const float* lnf_b   = (const float*)d_in[18];
    const float* head_w  = (const float*)d_in[19];
    const float* head_b  = (const float*)d_in[20];

    cudaFuncSetAttribute(hm_gemm, cudaFuncAttributeMaxDynamicSharedMemorySize, SMEM_DYN);

    float *xp, *qkvp;
    __half *a2p, *a2hp, *a2op, *a2fp, *a2cp;
    __half *w2p, *w1q, *w1o, *w1f1, *w1f2, *w2h;
    cudaGetSymbolAddress((void**)&xp,   g_x);
    cudaGetSymbolAddress((void**)&qkvp, g_qkv);
    cudaGetSymbolAddress((void**)&a2p,  a2_patch);
    cudaGetSymbolAddress((void**)&a2hp, a2_h);
    cudaGetSymbolAddress((void**)&a2op, a2_o);
    cudaGetSymbolAddress((void**)&a2fp, a2_ff);
    cudaGetSymbolAddress((void**)&a2cp, a2_cls);
    cudaGetSymbolAddress((void**)&w2p,  w2_patch);
    cudaGetSymbolAddress((void**)&w1q,  w1_qkv);
    cudaGetSymbolAddress((void**)&w1o,  w1_out);
    cudaGetSymbolAddress((void**)&w1f1, w1_ff1);
    cudaGetSymbolAddress((void**)&w1f2, w1_ff2);
    cudaGetSymbolAddress((void**)&w2h,  w2_head);

    {
        int n = Bv * IMGv * IMGv;
        mean_kernel<<<(n + 255) / 256, 256>>>(img);
        int np = MP * PDv;
        patch_build_kernel<<<(np + 255) / 256, 256>>>(img);
        int nw = DIMv * PDv;
        convw_kernel<<<dim3((nw + 255) / 256, 1), 256>>>(patch_w, w2p, DIMv, PDv);
    }
    run_hm(a2p, w2p, patch_b, nullptr, pos_emb, xp, nullptr,
           MP, DIMv, K2_PD, FLAG_REMAP);
    cls_init_kernel<<<Bv, DIMv>>>(cls_tok, pos_emb);

    {
        int n;
        n = 3 * INNERv * DIMv;
        convw1_kernel<<<dim3((n + 255) / 256, DEPTHv), 256>>>(qkv_w, w1q, n);
        n = DIMv * INNERv;
        convw1_kernel<<<dim3((n + 255) / 256, DEPTHv), 256>>>(out_w, w1o, n);
        n = MLPv * DIMv;
        convw1_kernel<<<dim3((n + 255) / 256, DEPTHv), 256>>>(ff_w1, w1f1, n);
        n = DIMv * MLPv;
        convw1_kernel<<<dim3((n + 255) / 256, DEPTHv), 256>>>(ff_w2, w1f2, n);
        n = NCLSv * DIMv;
        convw_kernel<<<dim3((n + 255) / 256, 1), 256>>>(head_w, w2h, NCLSv, DIMv);
    }

    for (int L = 0; L < DEPTHv; L++) {
        ln_split_kernel<<<TOK, 128>>>(xp, ln1_g + L * DIMv, ln1_b + L * DIMv, a2hp, DIMv, 0);
        run_hm(a2hp, w1q + (size_t)L * 3 * INNERv * DIMv, nullptr, nullptr, nullptr,
               qkvp, nullptr, TOK, 3 * INNERv, DIMv, 0);
        attn3<<<Bv * Hv, 224>>>(scale + L * Hv);
        run_hm(a2op, w1o + (size_t)L * DIMv * INNERv, out_b + L * DIMv, xp, nullptr,
               xp, nullptr, TOK, DIMv, INNERv, 0);
        ln_split_kernel<<<TOK, 128>>>(xp, ln2_g + L * DIMv, ln2_b + L * DIMv, a2hp, DIMv, 0);
        run_hm(a2hp, w1f1 + (size_t)L * MLPv * DIMv, ff_b1 + L * MLPv, nullptr, nullptr,
               nullptr, a2fp, TOK, MLPv, DIMv, FLAG_GELU | FLAG_HALF);
        run_hm(a2fp, w1f2 + (size_t)L * DIMv * MLPv, ff_b2 + L * DIMv, xp, nullptr,
               xp, nullptr, TOK, DIMv, MLPv, 0);
    }

    // final LN on cls rows -> 2-term split, then head
    ln_split_kernel<<<Bv, 128>>>(xp, lnf_g, lnf_b, a2cp, (long)Nv * DIMv, 1);
    run_hm(a2cp, w2h, head_b, nullptr, nullptr, (float*)d_out, nullptr,
           Bv, NCLSv, K2_DIM, 0);
}